// round 1
// baseline (speedup 1.0000x reference)
#include <cuda_runtime.h>
#include <cuda_bf16.h>
#include <math.h>

#define EMB 1024
#define DHEAD 64
#define BATCH 8
#define SEQ 2048
#define MTOT (BATCH * SEQ)   // 16384

// Scratch (no cudaMalloc allowed): Q, K, U = x@w_v1, O64 = attn@U
__device__ float g_Q[MTOT * DHEAD];
__device__ float g_K[MTOT * DHEAD];
__device__ float g_U[MTOT * DHEAD];
__device__ float g_O64[MTOT * DHEAD];

// ---------------------------------------------------------------------------
// Kernel 1: fused projections.  C[64x64 tile] = x[64 x 1024] @ W[1024 x 64]
// blockIdx.x: row tile (MTOT/64 = 256), blockIdx.y: which weight (0=Q,1=K,2=U)
// 256 threads as 16x16, each computing a 4x4 register tile, K-chunks of 16.
// ---------------------------------------------------------------------------
__global__ __launch_bounds__(256) void proj_kernel(
    const float* __restrict__ x,
    const float* __restrict__ w_q,
    const float* __restrict__ w_k,
    const float* __restrict__ w_v1)
{
    const float* w   = (blockIdx.y == 0) ? w_q : (blockIdx.y == 1) ? w_k : w_v1;
    float*       outg = (blockIdx.y == 0) ? g_Q : (blockIdx.y == 1) ? g_K : g_U;

    __shared__ float As[64][20];  // [row][k]   pad 20 -> 80B rows, float4 aligned
    __shared__ float Ws[16][68];  // [k][col]   pad 68 -> 272B rows, float4 aligned

    const int tid = threadIdx.x;
    const int ty  = tid >> 4;       // 0..15
    const int tx  = tid & 15;       // 0..15
    const int m0  = blockIdx.x * 64;

    float acc[4][4];
#pragma unroll
    for (int i = 0; i < 4; i++)
#pragma unroll
        for (int j = 0; j < 4; j++) acc[i][j] = 0.f;

    for (int k0 = 0; k0 < EMB; k0 += 16) {
        // load A tile 64x16 (one float4 per thread)
        {
            int row = tid >> 2, k4 = tid & 3;
            float4 v = *reinterpret_cast<const float4*>(
                &x[(size_t)(m0 + row) * EMB + k0 + k4 * 4]);
            *reinterpret_cast<float4*>(&As[row][k4 * 4]) = v;
        }
        // load W tile 16x64 (one float4 per thread)
        {
            int row = tid >> 4, c4 = tid & 15;
            float4 v = *reinterpret_cast<const float4*>(
                &w[(size_t)(k0 + row) * 64 + c4 * 4]);
            *reinterpret_cast<float4*>(&Ws[row][c4 * 4]) = v;
        }
        __syncthreads();

#pragma unroll
        for (int kk = 0; kk < 16; kk++) {
            float a[4], b[4];
#pragma unroll
            for (int i = 0; i < 4; i++) a[i] = As[ty * 4 + i][kk];
#pragma unroll
            for (int j = 0; j < 4; j++) b[j] = Ws[kk][tx * 4 + j];
#pragma unroll
            for (int i = 0; i < 4; i++)
#pragma unroll
                for (int j = 0; j < 4; j++) acc[i][j] = fmaf(a[i], b[j], acc[i][j]);
        }
        __syncthreads();
    }

#pragma unroll
    for (int i = 0; i < 4; i++) {
        int m = m0 + ty * 4 + i;
#pragma unroll
        for (int j = 0; j < 4; j++)
            outg[(size_t)m * 64 + tx * 4 + j] = acc[i][j];
    }
}

// ---------------------------------------------------------------------------
// Kernel 2: flash attention over 64x64 tiles, headdim 64, causal.
// grid = (SEQ/64, BATCH). 256 threads as 16x16, each owns 4 query rows x
// (4 score cols / 4 out dims). Online softmax; O64 = softmax(QK^T/8) @ U.
// Dynamic smem: Qs, Ks, Us, Ps each [64][68] + red[64][16].
// ---------------------------------------------------------------------------
#define TPAD 68
#define FLASH_SMEM_FLOATS (4 * 64 * TPAD + 64 * 16)
#define FLASH_SMEM_BYTES  (FLASH_SMEM_FLOATS * 4)

__global__ __launch_bounds__(256) void flash_kernel()
{
    extern __shared__ float smem[];
    float* Qs  = smem;
    float* Ks  = Qs + 64 * TPAD;
    float* Us  = Ks + 64 * TPAD;
    float* Ps  = Us + 64 * TPAD;
    float* red = Ps + 64 * TPAD;   // [64][16]

    const int tid = threadIdx.x;
    const int ty  = tid >> 4;
    const int tx  = tid & 15;
    const int qt  = blockIdx.x;           // query tile 0..31
    const int b   = blockIdx.y;           // batch
    const int q0  = qt * 64;
    const size_t base = (size_t)b * SEQ;

    // load Q tile (64x64)
    for (int i = tid; i < 64 * 16; i += 256) {
        int row = i >> 4, c4 = i & 15;
        float4 v = *reinterpret_cast<const float4*>(
            &g_Q[(base + q0 + row) * 64 + c4 * 4]);
        *reinterpret_cast<float4*>(&Qs[row * TPAD + c4 * 4]) = v;
    }

    float m_i[4], l_i[4], acc[4][4];
#pragma unroll
    for (int i = 0; i < 4; i++) {
        m_i[i] = -INFINITY; l_i[i] = 0.f;
#pragma unroll
        for (int c = 0; c < 4; c++) acc[i][c] = 0.f;
    }

    const float scale = 0.125f;  // 64^-0.5

    for (int kt = 0; kt <= qt; kt++) {
        __syncthreads();  // previous iter consumers done (also covers Q load on iter 0)
        // load K,U tiles (64x64 each)
        for (int i = tid; i < 64 * 16; i += 256) {
            int row = i >> 4, c4 = i & 15;
            size_t gidx = (base + (size_t)kt * 64 + row) * 64 + c4 * 4;
            *reinterpret_cast<float4*>(&Ks[row * TPAD + c4 * 4]) =
                *reinterpret_cast<const float4*>(&g_K[gidx]);
            *reinterpret_cast<float4*>(&Us[row * TPAD + c4 * 4]) =
                *reinterpret_cast<const float4*>(&g_U[gidx]);
        }
        __syncthreads();

        // S = Q @ K^T  (64x64 tile, each thread 4x4)
        float s[4][4];
#pragma unroll
        for (int i = 0; i < 4; i++)
#pragma unroll
            for (int j = 0; j < 4; j++) s[i][j] = 0.f;

#pragma unroll 4
        for (int k = 0; k < 64; k++) {
            float q[4], kv[4];
#pragma unroll
            for (int i = 0; i < 4; i++) q[i]  = Qs[(ty * 4 + i) * TPAD + k];
#pragma unroll
            for (int j = 0; j < 4; j++) kv[j] = Ks[(tx * 4 + j) * TPAD + k];
#pragma unroll
            for (int i = 0; i < 4; i++)
#pragma unroll
                for (int j = 0; j < 4; j++) s[i][j] = fmaf(q[i], kv[j], s[i][j]);
        }

        // scale + causal mask (only diagonal tile needs masking)
        if (kt == qt) {
#pragma unroll
            for (int i = 0; i < 4; i++) {
                int qi = ty * 4 + i;
#pragma unroll
                for (int j = 0; j < 4; j++) {
                    int kj = tx * 4 + j;
                    s[i][j] = (kj <= qi) ? s[i][j] * scale : -INFINITY;
                }
            }
        } else {
#pragma unroll
            for (int i = 0; i < 4; i++)
#pragma unroll
                for (int j = 0; j < 4; j++) s[i][j] *= scale;
        }

        // row max (partial over this thread's 4 cols, reduce across tx)
#pragma unroll
        for (int i = 0; i < 4; i++) {
            float pm = s[i][0];
#pragma unroll
            for (int j = 1; j < 4; j++) pm = fmaxf(pm, s[i][j]);
            red[(ty * 4 + i) * 16 + tx] = pm;
        }
        __syncthreads();
        float newm[4];
#pragma unroll
        for (int i = 0; i < 4; i++) {
            float rm = -INFINITY;
#pragma unroll
            for (int t = 0; t < 16; t++) rm = fmaxf(rm, red[(ty * 4 + i) * 16 + t]);
            newm[i] = fmaxf(m_i[i], rm);
        }
        __syncthreads();  // before red reuse

        // p = exp(s - newm), write P tile, partial row sums, rescale acc
#pragma unroll
        for (int i = 0; i < 4; i++) {
            float alpha = __expf(m_i[i] - newm[i]);
            m_i[i] = newm[i];
            float ps = 0.f;
#pragma unroll
            for (int j = 0; j < 4; j++) {
                float p = __expf(s[i][j] - newm[i]);
                Ps[(ty * 4 + i) * TPAD + tx * 4 + j] = p;
                ps += p;
            }
            red[(ty * 4 + i) * 16 + tx] = ps;
            l_i[i] *= alpha;
#pragma unroll
            for (int c = 0; c < 4; c++) acc[i][c] *= alpha;
        }
        __syncthreads();  // Ps + red visible
#pragma unroll
        for (int i = 0; i < 4; i++) {
            float rs = 0.f;
#pragma unroll
            for (int t = 0; t < 16; t++) rs += red[(ty * 4 + i) * 16 + t];
            l_i[i] += rs;
        }

        // acc += P @ U   (each thread: rows ty*4.., out dims tx*4..)
#pragma unroll 4
        for (int k = 0; k < 64; k++) {
            float p[4], u[4];
#pragma unroll
            for (int i = 0; i < 4; i++) p[i] = Ps[(ty * 4 + i) * TPAD + k];
#pragma unroll
            for (int c = 0; c < 4; c++) u[c] = Us[k * TPAD + tx * 4 + c];
#pragma unroll
            for (int i = 0; i < 4; i++)
#pragma unroll
                for (int c = 0; c < 4; c++) acc[i][c] = fmaf(p[i], u[c], acc[i][c]);
        }
    }

    // write O64 = acc / l
#pragma unroll
    for (int i = 0; i < 4; i++) {
        float inv = 1.0f / l_i[i];
        size_t m = base + q0 + ty * 4 + i;
#pragma unroll
        for (int c = 0; c < 4; c++)
            g_O64[m * 64 + tx * 4 + c] = acc[i][c] * inv;
    }
}

// ---------------------------------------------------------------------------
// Kernel 3: out[m, :] = O64[m, 0:64] @ w_v2[64, 1024]
// One block per row; 256 threads x 4 cols (float4). w_v2 (256KB) lives in L2.
// ---------------------------------------------------------------------------
__global__ __launch_bounds__(256) void outproj_kernel(
    const float* __restrict__ w_v2, float* __restrict__ out)
{
    __shared__ float o[64];
    const int m = blockIdx.x;
    const int tid = threadIdx.x;
    if (tid < 64) o[tid] = g_O64[(size_t)m * 64 + tid];
    __syncthreads();

    const int e0 = tid * 4;
    float4 acc = make_float4(0.f, 0.f, 0.f, 0.f);
#pragma unroll 8
    for (int k = 0; k < 64; k++) {
        float ok = o[k];
        float4 w = *reinterpret_cast<const float4*>(&w_v2[(size_t)k * EMB + e0]);
        acc.x = fmaf(ok, w.x, acc.x);
        acc.y = fmaf(ok, w.y, acc.y);
        acc.z = fmaf(ok, w.z, acc.z);
        acc.w = fmaf(ok, w.w, acc.w);
    }
    *reinterpret_cast<float4*>(&out[(size_t)m * EMB + e0]) = acc;
}

// ---------------------------------------------------------------------------
extern "C" void kernel_launch(void* const* d_in, const int* in_sizes, int n_in,
                              void* d_out, int out_size)
{
    const float* x    = (const float*)d_in[0];
    const float* w_q  = (const float*)d_in[1];
    const float* w_k  = (const float*)d_in[2];
    const float* w_v1 = (const float*)d_in[3];
    const float* w_v2 = (const float*)d_in[4];
    float* out = (float*)d_out;

    (void)in_sizes; (void)n_in; (void)out_size;

    cudaFuncSetAttribute(flash_kernel,
                         cudaFuncAttributeMaxDynamicSharedMemorySize,
                         FLASH_SMEM_BYTES);

    proj_kernel<<<dim3(MTOT / 64, 3), 256>>>(x, w_q, w_k, w_v1);
    flash_kernel<<<dim3(SEQ / 64, BATCH), 256, FLASH_SMEM_BYTES>>>();
    outproj_kernel<<<MTOT, 256>>>(w_v2, out);
}

// round 3
// speedup vs baseline: 3.5186x; 3.5186x over previous
#include <cuda_runtime.h>
#include <cuda_bf16.h>
#include <math.h>
#include <stdint.h>

#define EMB 1024
#define DHEAD 64
#define BATCH 8
#define SEQ 2048
#define MTOT (BATCH * SEQ)   // 16384

// ---------------------------------------------------------------------------
// Scratch (__device__ globals; no cudaMalloc allowed)
// ---------------------------------------------------------------------------
__device__ __nv_bfloat16 g_Qh[MTOT * DHEAD], g_Ql[MTOT * DHEAD]; // pre-scaled 0.125*log2e
__device__ __nv_bfloat16 g_Kh[MTOT * DHEAD], g_Kl[MTOT * DHEAD];
__device__ __nv_bfloat16 g_Uh[MTOT * DHEAD], g_Ul[MTOT * DHEAD]; // U = x@w_v1, [s][d]
__device__ __nv_bfloat16 g_Oh[MTOT * DHEAD], g_Ol[MTOT * DHEAD]; // attn output (pre w_v2)
__device__ __nv_bfloat16 g_Wh[3 * EMB * DHEAD], g_Wl[3 * EMB * DHEAD]; // wq|wk|wv1
__device__ __nv_bfloat16 g_W2h[DHEAD * EMB], g_W2l[DHEAD * EMB];

// ---------------------------------------------------------------------------
// Helpers
// ---------------------------------------------------------------------------
__device__ __forceinline__ uint32_t smem_u32(const void* p) {
    uint32_t a;
    asm("{ .reg .u64 t; cvta.to.shared.u64 t, %1; cvt.u32.u64 %0, t; }" : "=r"(a) : "l"(p));
    return a;
}
__device__ __forceinline__ void ldsm4(uint32_t* r, uint32_t a) {
    asm volatile("ldmatrix.sync.aligned.m8n8.x4.shared.b16 {%0,%1,%2,%3}, [%4];"
                 : "=r"(r[0]), "=r"(r[1]), "=r"(r[2]), "=r"(r[3]) : "r"(a));
}
__device__ __forceinline__ void ldsm4t(uint32_t* r, uint32_t a) {
    asm volatile("ldmatrix.sync.aligned.m8n8.x4.trans.shared.b16 {%0,%1,%2,%3}, [%4];"
                 : "=r"(r[0]), "=r"(r[1]), "=r"(r[2]), "=r"(r[3]) : "r"(a));
}
__device__ __forceinline__ void mma_bf16(float* c, const uint32_t* a, uint32_t b0, uint32_t b1) {
    asm volatile("mma.sync.aligned.m16n8k16.row.col.f32.bf16.bf16.f32 "
                 "{%0,%1,%2,%3}, {%4,%5,%6,%7}, {%8,%9}, {%0,%1,%2,%3};"
                 : "+f"(c[0]), "+f"(c[1]), "+f"(c[2]), "+f"(c[3])
                 : "r"(a[0]), "r"(a[1]), "r"(a[2]), "r"(a[3]), "r"(b0), "r"(b1));
}
// pack (v0 -> low half, v1 -> high half)
__device__ __forceinline__ uint32_t packbf(float v0, float v1) {
    uint32_t r;
    asm("cvt.rn.bf16x2.f32 %0, %1, %2;" : "=r"(r) : "f"(v1), "f"(v0));
    return r;
}
// split pair into bf16 hi + residual lo
__device__ __forceinline__ void split2(float v0, float v1, uint32_t& hi, uint32_t& lo) {
    hi = packbf(v0, v1);
    float h0 = __uint_as_float(hi << 16);
    float h1 = __uint_as_float(hi & 0xFFFF0000u);
    lo = packbf(v0 - h0, v1 - h1);
}
__device__ __forceinline__ float ex2(float x) {
    float r;
    asm("ex2.approx.ftz.f32 %0, %1;" : "=f"(r) : "f"(x));
    return r;
}

// ---------------------------------------------------------------------------
// Kernel 0: convert weights to bf16 hi/lo (262144 elems, 2 per thread)
// ---------------------------------------------------------------------------
__global__ __launch_bounds__(256) void convw_kernel(
    const float* __restrict__ wq, const float* __restrict__ wk,
    const float* __restrict__ wv1, const float* __restrict__ wv2)
{
    int p = (blockIdx.x * 256 + threadIdx.x) * 2;
    float v0, v1;
    __nv_bfloat16 *dh, *dl;
    int off;
    if (p < 3 * EMB * DHEAD) {
        const float* src = (p < EMB * DHEAD) ? wq : (p < 2 * EMB * DHEAD) ? wk : wv1;
        int e = p & (EMB * DHEAD - 1);
        v0 = src[e]; v1 = src[e + 1];
        dh = g_Wh; dl = g_Wl; off = p;
    } else {
        int e = p - 3 * EMB * DHEAD;
        v0 = wv2[e]; v1 = wv2[e + 1];
        dh = g_W2h; dl = g_W2l; off = e;
    }
    uint32_t hi, lo;
    split2(v0, v1, hi, lo);
    *reinterpret_cast<uint32_t*>(dh + off) = hi;
    *reinterpret_cast<uint32_t*>(dl + off) = lo;
}

// ---------------------------------------------------------------------------
// Kernel 1: fused projections via mma.sync. Block = 128 rows x all 3 weights.
// x converted fp32 -> bf16 hi/lo in-kernel. K-chunks of 32.
// ---------------------------------------------------------------------------
#define PJ_XPITCH 80
#define PJ_WPITCH 144
#define PJ_XH 0
#define PJ_XL (128 * PJ_XPITCH)                   // 10240
#define PJ_WH (2 * 128 * PJ_XPITCH)               // 20480
#define PJ_WTILE (32 * PJ_WPITCH)                 // 4608
#define PJ_WL (PJ_WH + 3 * PJ_WTILE)              // 34304
#define PJ_SMEM (PJ_WL + 3 * PJ_WTILE)            // 48128

__global__ __launch_bounds__(256) void proj_kernel(const float* __restrict__ x)
{
    extern __shared__ char sm[];
    const uint32_t sb = smem_u32(sm);
    const int tid = threadIdx.x, w = tid >> 5, lane = tid & 31;
    const int g = lane >> 2, tig = lane & 3;
    const int m0 = blockIdx.x * 128;

    float acc[3][8][4];
#pragma unroll
    for (int t = 0; t < 3; t++)
#pragma unroll
        for (int j = 0; j < 8; j++)
#pragma unroll
            for (int q = 0; q < 4; q++) acc[t][j][q] = 0.f;

    const int mrow = w * 16 + (lane & 7) + ((lane >> 3) & 1) * 8;
    const int akb = (lane >> 4) * 16;
    const int krow = (lane >> 4) * 16 + ((lane >> 3) & 1) * 8 + (lane & 7);

    for (int k0 = 0; k0 < EMB; k0 += 32) {
        // x fp32 tile -> bf16 hi/lo smem
#pragma unroll
        for (int i = tid; i < 128 * 8; i += 256) {
            int r = i >> 3, c = (i & 7) * 4;
            float4 v = *reinterpret_cast<const float4*>(&x[(size_t)(m0 + r) * EMB + k0 + c]);
            uint32_t h0, l0, h1, l1;
            split2(v.x, v.y, h0, l0);
            split2(v.z, v.w, h1, l1);
            uint32_t* ph = reinterpret_cast<uint32_t*>(sm + PJ_XH + r * PJ_XPITCH + c * 2);
            ph[0] = h0; ph[1] = h1;
            uint32_t* pl = reinterpret_cast<uint32_t*>(sm + PJ_XL + r * PJ_XPITCH + c * 2);
            pl[0] = l0; pl[1] = l1;
        }
        // weight tiles (3 x 32 x 64), hi/lo
#pragma unroll
        for (int i = tid; i < 768; i += 256) {
            int t = i >> 8, r = (i >> 3) & 31, c = i & 7;
            size_t gi = (size_t)t * EMB * 64 + (size_t)(k0 + r) * 64 + c * 8;
            *reinterpret_cast<uint4*>(sm + PJ_WH + t * PJ_WTILE + r * PJ_WPITCH + c * 16) =
                *reinterpret_cast<const uint4*>(g_Wh + gi);
            *reinterpret_cast<uint4*>(sm + PJ_WL + t * PJ_WTILE + r * PJ_WPITCH + c * 16) =
                *reinterpret_cast<const uint4*>(g_Wl + gi);
        }
        __syncthreads();

        uint32_t ah[2][4], al[2][4];
#pragma unroll
        for (int kk = 0; kk < 2; kk++) {
            ldsm4(ah[kk], sb + PJ_XH + mrow * PJ_XPITCH + kk * 32 + akb);
            ldsm4(al[kk], sb + PJ_XL + mrow * PJ_XPITCH + kk * 32 + akb);
        }
#pragma unroll
        for (int t = 0; t < 3; t++) {
#pragma unroll
            for (int j = 0; j < 8; j++) {
                uint32_t bh[4], bl[4];
                ldsm4t(bh, sb + PJ_WH + t * PJ_WTILE + krow * PJ_WPITCH + j * 16);
                ldsm4t(bl, sb + PJ_WL + t * PJ_WTILE + krow * PJ_WPITCH + j * 16);
                float* c = acc[t][j];
                mma_bf16(c, ah[0], bh[0], bh[1]);
                mma_bf16(c, ah[1], bh[2], bh[3]);
                mma_bf16(c, ah[0], bl[0], bl[1]);
                mma_bf16(c, ah[1], bl[2], bl[3]);
                mma_bf16(c, al[0], bh[0], bh[1]);
                mma_bf16(c, al[1], bh[2], bh[3]);
            }
        }
        __syncthreads();
    }

    // epilogue: bf16 hi/lo, Q scaled
#pragma unroll
    for (int t = 0; t < 3; t++) {
        __nv_bfloat16* dh = (t == 0) ? g_Qh : (t == 1) ? g_Kh : g_Uh;
        __nv_bfloat16* dl = (t == 0) ? g_Ql : (t == 1) ? g_Kl : g_Ul;
        const float scl = (t == 0) ? 0.18033688f : 1.0f;  // 0.125 * log2(e)
#pragma unroll
        for (int j = 0; j < 8; j++) {
            int col = j * 8 + tig * 2;
            size_t r0 = (size_t)(m0 + w * 16 + g);
            uint32_t h, l;
            split2(acc[t][j][0] * scl, acc[t][j][1] * scl, h, l);
            *reinterpret_cast<uint32_t*>(dh + r0 * 64 + col) = h;
            *reinterpret_cast<uint32_t*>(dl + r0 * 64 + col) = l;
            split2(acc[t][j][2] * scl, acc[t][j][3] * scl, h, l);
            *reinterpret_cast<uint32_t*>(dh + (r0 + 8) * 64 + col) = h;
            *reinterpret_cast<uint32_t*>(dl + (r0 + 8) * 64 + col) = l;
        }
    }
}

// ---------------------------------------------------------------------------
// Kernel 2: FA2-style flash attention via mma.sync.
// grid (SEQ/64, BATCH), 128 threads (4 warps), each warp a 16-row band.
// No-max softmax: p = exp2(s) with Q pre-scaled; scores bounded.
// ---------------------------------------------------------------------------
#define FL_PITCH 144
#define FL_TILE (64 * FL_PITCH)     // 9216
#define FL_KH 0
#define FL_KL FL_TILE
#define FL_UH (2 * FL_TILE)
#define FL_UL (3 * FL_TILE)
#define FL_SMEM (4 * FL_TILE)       // 36864

__global__ __launch_bounds__(128) void flash_kernel()
{
    extern __shared__ char sm[];
    const uint32_t sb = smem_u32(sm);
    const int tid = threadIdx.x, w = tid >> 5, lane = tid & 31;
    const int g = lane >> 2, tig = lane & 3;
    const int qt = blockIdx.x, b = blockIdx.y;
    const int q0 = qt * 64;
    const size_t base = (size_t)b * SEQ;

    // stage Q (64x64 hi/lo) in K buffers, pull fragments
    for (int i = tid; i < 64 * 8; i += 128) {
        int r = i >> 3, c = i & 7;
        size_t gq = (base + q0 + r) * 64 + c * 8;
        *reinterpret_cast<uint4*>(sm + FL_KH + r * FL_PITCH + c * 16) =
            *reinterpret_cast<const uint4*>(g_Qh + gq);
        *reinterpret_cast<uint4*>(sm + FL_KL + r * FL_PITCH + c * 16) =
            *reinterpret_cast<const uint4*>(g_Ql + gq);
    }
    __syncthreads();
    uint32_t qh[4][4], ql[4][4];
    {
        const int mrow = w * 16 + (lane & 7) + ((lane >> 3) & 1) * 8;
        const int akb = (lane >> 4) * 16;
#pragma unroll
        for (int kk = 0; kk < 4; kk++) {
            ldsm4(qh[kk], sb + FL_KH + mrow * FL_PITCH + kk * 32 + akb);
            ldsm4(ql[kk], sb + FL_KL + mrow * FL_PITCH + kk * 32 + akb);
        }
    }
    __syncthreads();

    float o[8][4];
#pragma unroll
    for (int j = 0; j < 8; j++)
#pragma unroll
        for (int q = 0; q < 4; q++) o[j][q] = 0.f;
    float l0 = 0.f, l1 = 0.f;

    const int row0 = q0 + w * 16 + g, row1 = row0 + 8;
    const int nk = qt + 1;

    for (int kt = 0; kt < nk; kt++) {
        const int k0 = kt * 64;
        for (int i = tid; i < 64 * 8; i += 128) {
            int r = i >> 3, c = i & 7;
            size_t gk = (base + k0 + r) * 64 + c * 8;
            uint32_t d = r * FL_PITCH + c * 16;
            *reinterpret_cast<uint4*>(sm + FL_KH + d) = *reinterpret_cast<const uint4*>(g_Kh + gk);
            *reinterpret_cast<uint4*>(sm + FL_KL + d) = *reinterpret_cast<const uint4*>(g_Kl + gk);
            *reinterpret_cast<uint4*>(sm + FL_UH + d) = *reinterpret_cast<const uint4*>(g_Uh + gk);
            *reinterpret_cast<uint4*>(sm + FL_UL + d) = *reinterpret_cast<const uint4*>(g_Ul + gk);
        }
        __syncthreads();

        // S = Q K^T  (split-bf16, 3 passes)
        float s[8][4];
#pragma unroll
        for (int j = 0; j < 8; j++) {
#pragma unroll
            for (int q = 0; q < 4; q++) s[j][q] = 0.f;
            uint32_t a0 = sb + FL_KH + (j * 8 + (lane & 7)) * FL_PITCH + (lane >> 3) * 16;
            uint32_t a1 = sb + FL_KL + (j * 8 + (lane & 7)) * FL_PITCH + (lane >> 3) * 16;
            uint32_t bh[4], bh2[4], bl[4], bl2[4];
            ldsm4(bh, a0); ldsm4(bh2, a0 + 64);
            ldsm4(bl, a1); ldsm4(bl2, a1 + 64);
            float* c = s[j];
            mma_bf16(c, qh[0], bh[0], bh[1]);
            mma_bf16(c, qh[1], bh[2], bh[3]);
            mma_bf16(c, qh[2], bh2[0], bh2[1]);
            mma_bf16(c, qh[3], bh2[2], bh2[3]);
            mma_bf16(c, qh[0], bl[0], bl[1]);
            mma_bf16(c, qh[1], bl[2], bl[3]);
            mma_bf16(c, qh[2], bl2[0], bl2[1]);
            mma_bf16(c, qh[3], bl2[2], bl2[3]);
            mma_bf16(c, ql[0], bh[0], bh[1]);
            mma_bf16(c, ql[1], bh[2], bh[3]);
            mma_bf16(c, ql[2], bh2[0], bh2[1]);
            mma_bf16(c, ql[3], bh2[2], bh2[3]);
        }

        // softmax (no running max): p = exp2(s), causal mask on diagonal tile
        const bool diag = (kt == qt);
#pragma unroll
        for (int j = 0; j < 8; j++) {
            int cb = k0 + j * 8 + tig * 2;
            float p0 = ex2(s[j][0]), p1 = ex2(s[j][1]);
            float p2 = ex2(s[j][2]), p3 = ex2(s[j][3]);
            if (diag) {
                if (cb > row0) p0 = 0.f;
                if (cb + 1 > row0) p1 = 0.f;
                if (cb > row1) p2 = 0.f;
                if (cb + 1 > row1) p3 = 0.f;
            }
            s[j][0] = p0; s[j][1] = p1; s[j][2] = p2; s[j][3] = p3;
            l0 += p0 + p1;
            l1 += p2 + p3;
        }

        // P fragments (C-frag -> A-frag layout identity), hi/lo
        uint32_t ph[4][4], pl[4][4];
#pragma unroll
        for (int kk = 0; kk < 4; kk++) {
            split2(s[2 * kk][0], s[2 * kk][1], ph[kk][0], pl[kk][0]);
            split2(s[2 * kk][2], s[2 * kk][3], ph[kk][1], pl[kk][1]);
            split2(s[2 * kk + 1][0], s[2 * kk + 1][1], ph[kk][2], pl[kk][2]);
            split2(s[2 * kk + 1][2], s[2 * kk + 1][3], ph[kk][3], pl[kk][3]);
        }

        // O += P U (split-bf16, 3 passes)
#pragma unroll
        for (int jp = 0; jp < 4; jp++) {
#pragma unroll
            for (int kk = 0; kk < 4; kk++) {
                int krow = kk * 16 + ((lane >> 3) & 1) * 8 + (lane & 7);
                int nbyte = (jp * 2 + (lane >> 4)) * 16;
                uint32_t bh[4], bl[4];
                ldsm4t(bh, sb + FL_UH + krow * FL_PITCH + nbyte);
                ldsm4t(bl, sb + FL_UL + krow * FL_PITCH + nbyte);
                mma_bf16(o[2 * jp], ph[kk], bh[0], bh[1]);
                mma_bf16(o[2 * jp + 1], ph[kk], bh[2], bh[3]);
                mma_bf16(o[2 * jp], ph[kk], bl[0], bl[1]);
                mma_bf16(o[2 * jp + 1], ph[kk], bl[2], bl[3]);
                mma_bf16(o[2 * jp], pl[kk], bh[0], bh[1]);
                mma_bf16(o[2 * jp + 1], pl[kk], bh[2], bh[3]);
            }
        }
        __syncthreads();
    }

    // reduce row sums across the 4-lane quad (same rows)
    l0 += __shfl_xor_sync(0xffffffffu, l0, 1);
    l0 += __shfl_xor_sync(0xffffffffu, l0, 2);
    l1 += __shfl_xor_sync(0xffffffffu, l1, 1);
    l1 += __shfl_xor_sync(0xffffffffu, l1, 2);
    const float i0 = 1.0f / l0, i1 = 1.0f / l1;

#pragma unroll
    for (int j = 0; j < 8; j++) {
        int col = j * 8 + tig * 2;
        size_t r0 = base + q0 + w * 16 + g;
        uint32_t h, l;
        split2(o[j][0] * i0, o[j][1] * i0, h, l);
        *reinterpret_cast<uint32_t*>(g_Oh + r0 * 64 + col) = h;
        *reinterpret_cast<uint32_t*>(g_Ol + r0 * 64 + col) = l;
        split2(o[j][2] * i1, o[j][3] * i1, h, l);
        *reinterpret_cast<uint32_t*>(g_Oh + (r0 + 8) * 64 + col) = h;
        *reinterpret_cast<uint32_t*>(g_Ol + (r0 + 8) * 64 + col) = l;
    }
}

// ---------------------------------------------------------------------------
// Kernel 3: out[128x128 tile] = O64[128x64] @ w_v2[64x128] via mma.sync.
// ---------------------------------------------------------------------------
#define OP_OPITCH 144
#define OP_WPITCH 272
#define OP_OH 0
#define OP_OL (128 * OP_OPITCH)                 // 18432
#define OP_WH (2 * 128 * OP_OPITCH)             // 36864
#define OP_WL (OP_WH + 64 * OP_WPITCH)          // 54272
#define OP_SMEM (OP_WL + 64 * OP_WPITCH)        // 71680

__global__ __launch_bounds__(256) void outproj_kernel(float* __restrict__ out)
{
    extern __shared__ char sm[];
    const uint32_t sb = smem_u32(sm);
    const int tid = threadIdx.x, w = tid >> 5, lane = tid & 31;
    const int g = lane >> 2, tig = lane & 3;
    const int row0 = blockIdx.y * 128, col0 = blockIdx.x * 128;

    for (int i = tid; i < 128 * 8; i += 256) {
        int r = i >> 3, c = i & 7;
        size_t gi = (size_t)(row0 + r) * 64 + c * 8;
        *reinterpret_cast<uint4*>(sm + OP_OH + r * OP_OPITCH + c * 16) =
            *reinterpret_cast<const uint4*>(g_Oh + gi);
        *reinterpret_cast<uint4*>(sm + OP_OL + r * OP_OPITCH + c * 16) =
            *reinterpret_cast<const uint4*>(g_Ol + gi);
    }
    for (int i = tid; i < 64 * 16; i += 256) {
        int r = i >> 4, c = i & 15;
        size_t gi = (size_t)r * EMB + col0 + c * 8;
        *reinterpret_cast<uint4*>(sm + OP_WH + r * OP_WPITCH + c * 16) =
            *reinterpret_cast<const uint4*>(g_W2h + gi);
        *reinterpret_cast<uint4*>(sm + OP_WL + r * OP_WPITCH + c * 16) =
            *reinterpret_cast<const uint4*>(g_W2l + gi);
    }
    __syncthreads();

    uint32_t ah[4][4], al[4][4];
    const int mrow = w * 16 + (lane & 7) + ((lane >> 3) & 1) * 8;
    const int akb = (lane >> 4) * 16;
#pragma unroll
    for (int kk = 0; kk < 4; kk++) {
        ldsm4(ah[kk], sb + OP_OH + mrow * OP_OPITCH + kk * 32 + akb);
        ldsm4(al[kk], sb + OP_OL + mrow * OP_OPITCH + kk * 32 + akb);
    }

#pragma unroll
    for (int j = 0; j < 16; j++) {
        float c[4] = {0.f, 0.f, 0.f, 0.f};
#pragma unroll
        for (int kp = 0; kp < 2; kp++) {
            int krow = kp * 32 + (lane >> 4) * 16 + ((lane >> 3) & 1) * 8 + (lane & 7);
            uint32_t bh[4], bl[4];
            ldsm4t(bh, sb + OP_WH + krow * OP_WPITCH + j * 16);
            ldsm4t(bl, sb + OP_WL + krow * OP_WPITCH + j * 16);
            mma_bf16(c, ah[2 * kp], bh[0], bh[1]);
            mma_bf16(c, ah[2 * kp + 1], bh[2], bh[3]);
            mma_bf16(c, ah[2 * kp], bl[0], bl[1]);
            mma_bf16(c, ah[2 * kp + 1], bl[2], bl[3]);
            mma_bf16(c, al[2 * kp], bh[0], bh[1]);
            mma_bf16(c, al[2 * kp + 1], bh[2], bh[3]);
        }
        int col = col0 + j * 8 + tig * 2;
        int r = row0 + w * 16 + g;
        *reinterpret_cast<float2*>(&out[(size_t)r * EMB + col]) = make_float2(c[0], c[1]);
        *reinterpret_cast<float2*>(&out[(size_t)(r + 8) * EMB + col]) = make_float2(c[2], c[3]);
    }
}

// ---------------------------------------------------------------------------
extern "C" void kernel_launch(void* const* d_in, const int* in_sizes, int n_in,
                              void* d_out, int out_size)
{
    const float* x    = (const float*)d_in[0];
    const float* w_q  = (const float*)d_in[1];
    const float* w_k  = (const float*)d_in[2];
    const float* w_v1 = (const float*)d_in[3];
    const float* w_v2 = (const float*)d_in[4];
    float* out = (float*)d_out;
    (void)in_sizes; (void)n_in; (void)out_size;

    cudaFuncSetAttribute(proj_kernel, cudaFuncAttributeMaxDynamicSharedMemorySize, PJ_SMEM);
    cudaFuncSetAttribute(flash_kernel, cudaFuncAttributeMaxDynamicSharedMemorySize, FL_SMEM);
    cudaFuncSetAttribute(outproj_kernel, cudaFuncAttributeMaxDynamicSharedMemorySize, OP_SMEM);

    convw_kernel<<<512, 256>>>(w_q, w_k, w_v1, w_v2);
    proj_kernel<<<MTOT / 128, 256, PJ_SMEM>>>(x);
    flash_kernel<<<dim3(SEQ / 64, BATCH), 128, FL_SMEM>>>();
    outproj_kernel<<<dim3(EMB / 128, MTOT / 128), 256, OP_SMEM>>>(out);
}

// round 4
// speedup vs baseline: 4.2883x; 1.2187x over previous
#include <cuda_runtime.h>
#include <cuda_bf16.h>
#include <math.h>
#include <stdint.h>

#define EMB 1024
#define DHEAD 64
#define BATCH 8
#define SEQ 2048
#define MTOT (BATCH * SEQ)   // 16384

// ---------------------------------------------------------------------------
// Scratch (__device__ globals; no cudaMalloc allowed)
// ---------------------------------------------------------------------------
__device__ __nv_bfloat16 g_Qh[MTOT * DHEAD], g_Ql[MTOT * DHEAD]; // pre-scaled 0.125*log2e
__device__ __nv_bfloat16 g_Kh[MTOT * DHEAD], g_Kl[MTOT * DHEAD];
__device__ __nv_bfloat16 g_Uh[MTOT * DHEAD], g_Ul[MTOT * DHEAD]; // U = x@w_v1
__device__ __nv_bfloat16 g_Oh[MTOT * DHEAD], g_Ol[MTOT * DHEAD]; // attn out (pre w_v2)
__device__ __nv_bfloat16 g_Wh[3 * EMB * DHEAD], g_Wl[3 * EMB * DHEAD]; // wq|wk|wv1
__device__ __nv_bfloat16 g_W2h[DHEAD * EMB], g_W2l[DHEAD * EMB];
// split-KV partials
__device__ float g_Op0[MTOT * DHEAD], g_Op1[MTOT * DHEAD];
__device__ float g_l0[MTOT], g_l1[MTOT];

// ---------------------------------------------------------------------------
// Helpers
// ---------------------------------------------------------------------------
__device__ __forceinline__ uint32_t smem_u32(const void* p) {
    uint32_t a;
    asm("{ .reg .u64 t; cvta.to.shared.u64 t, %1; cvt.u32.u64 %0, t; }" : "=r"(a) : "l"(p));
    return a;
}
__device__ __forceinline__ void ldsm4(uint32_t* r, uint32_t a) {
    asm volatile("ldmatrix.sync.aligned.m8n8.x4.shared.b16 {%0,%1,%2,%3}, [%4];"
                 : "=r"(r[0]), "=r"(r[1]), "=r"(r[2]), "=r"(r[3]) : "r"(a));
}
__device__ __forceinline__ void ldsm4t(uint32_t* r, uint32_t a) {
    asm volatile("ldmatrix.sync.aligned.m8n8.x4.trans.shared.b16 {%0,%1,%2,%3}, [%4];"
                 : "=r"(r[0]), "=r"(r[1]), "=r"(r[2]), "=r"(r[3]) : "r"(a));
}
__device__ __forceinline__ void mma_bf16(float* c, const uint32_t* a, uint32_t b0, uint32_t b1) {
    asm volatile("mma.sync.aligned.m16n8k16.row.col.f32.bf16.bf16.f32 "
                 "{%0,%1,%2,%3}, {%4,%5,%6,%7}, {%8,%9}, {%0,%1,%2,%3};"
                 : "+f"(c[0]), "+f"(c[1]), "+f"(c[2]), "+f"(c[3])
                 : "r"(a[0]), "r"(a[1]), "r"(a[2]), "r"(a[3]), "r"(b0), "r"(b1));
}
__device__ __forceinline__ uint32_t packbf(float v0, float v1) {
    uint32_t r;
    asm("cvt.rn.bf16x2.f32 %0, %1, %2;" : "=r"(r) : "f"(v1), "f"(v0));
    return r;
}
__device__ __forceinline__ void split2(float v0, float v1, uint32_t& hi, uint32_t& lo) {
    hi = packbf(v0, v1);
    float h0 = __uint_as_float(hi << 16);
    float h1 = __uint_as_float(hi & 0xFFFF0000u);
    lo = packbf(v0 - h0, v1 - h1);
}
__device__ __forceinline__ float ex2(float x) {
    float r;
    asm("ex2.approx.ftz.f32 %0, %1;" : "=f"(r) : "f"(x));
    return r;
}

// ---------------------------------------------------------------------------
// Kernel 0: convert weights to bf16 hi/lo
// ---------------------------------------------------------------------------
__global__ __launch_bounds__(256) void convw_kernel(
    const float* __restrict__ wq, const float* __restrict__ wk,
    const float* __restrict__ wv1, const float* __restrict__ wv2)
{
    int p = (blockIdx.x * 256 + threadIdx.x) * 2;
    float v0, v1;
    __nv_bfloat16 *dh, *dl;
    int off;
    if (p < 3 * EMB * DHEAD) {
        const float* src = (p < EMB * DHEAD) ? wq : (p < 2 * EMB * DHEAD) ? wk : wv1;
        int e = p & (EMB * DHEAD - 1);
        v0 = src[e]; v1 = src[e + 1];
        dh = g_Wh; dl = g_Wl; off = p;
    } else {
        int e = p - 3 * EMB * DHEAD;
        v0 = wv2[e]; v1 = wv2[e + 1];
        dh = g_W2h; dl = g_W2l; off = e;
    }
    uint32_t hi, lo;
    split2(v0, v1, hi, lo);
    *reinterpret_cast<uint32_t*>(dh + off) = hi;
    *reinterpret_cast<uint32_t*>(dl + off) = lo;
}

// ---------------------------------------------------------------------------
// Kernel 1: fused projections via mma.sync. 64-row tiles, 128 threads,
// grid = MTOT/64 = 256 blocks (full SM coverage). K-chunks of 32.
// ---------------------------------------------------------------------------
#define PJ_XPITCH 80
#define PJ_WPITCH 144
#define PJ_XH 0
#define PJ_XL (64 * PJ_XPITCH)            // 5120
#define PJ_WH (2 * 64 * PJ_XPITCH)        // 10240
#define PJ_WTILE (32 * PJ_WPITCH)         // 4608
#define PJ_WL (PJ_WH + 3 * PJ_WTILE)      // 24064
#define PJ_SMEM (PJ_WL + 3 * PJ_WTILE)    // 37888

__global__ __launch_bounds__(128) void proj_kernel(const float* __restrict__ x)
{
    extern __shared__ char sm[];
    const uint32_t sb = smem_u32(sm);
    const int tid = threadIdx.x, w = tid >> 5, lane = tid & 31;
    const int gr = lane >> 2, tig = lane & 3;
    const int m0 = blockIdx.x * 64;

    float acc[3][8][4];
#pragma unroll
    for (int t = 0; t < 3; t++)
#pragma unroll
        for (int j = 0; j < 8; j++)
#pragma unroll
            for (int q = 0; q < 4; q++) acc[t][j][q] = 0.f;

    const int mrow = w * 16 + (lane & 7) + ((lane >> 3) & 1) * 8;
    const int akb = (lane >> 4) * 16;
    const int krow = (lane >> 4) * 16 + ((lane >> 3) & 1) * 8 + (lane & 7);

    for (int k0 = 0; k0 < EMB; k0 += 32) {
        // x fp32 tile (64x32) -> bf16 hi/lo smem
#pragma unroll
        for (int i = tid; i < 64 * 8; i += 128) {
            int r = i >> 3, c = (i & 7) * 4;
            float4 v = *reinterpret_cast<const float4*>(&x[(size_t)(m0 + r) * EMB + k0 + c]);
            uint32_t h0, l0, h1, l1;
            split2(v.x, v.y, h0, l0);
            split2(v.z, v.w, h1, l1);
            uint32_t* ph = reinterpret_cast<uint32_t*>(sm + PJ_XH + r * PJ_XPITCH + c * 2);
            ph[0] = h0; ph[1] = h1;
            uint32_t* pl = reinterpret_cast<uint32_t*>(sm + PJ_XL + r * PJ_XPITCH + c * 2);
            pl[0] = l0; pl[1] = l1;
        }
        // weight tiles (3 x 32 x 64), hi/lo
#pragma unroll
        for (int i = tid; i < 768; i += 128) {
            int t = i >> 8, r = (i >> 3) & 31, c = i & 7;
            size_t gi = (size_t)t * EMB * 64 + (size_t)(k0 + r) * 64 + c * 8;
            *reinterpret_cast<uint4*>(sm + PJ_WH + t * PJ_WTILE + r * PJ_WPITCH + c * 16) =
                *reinterpret_cast<const uint4*>(g_Wh + gi);
            *reinterpret_cast<uint4*>(sm + PJ_WL + t * PJ_WTILE + r * PJ_WPITCH + c * 16) =
                *reinterpret_cast<const uint4*>(g_Wl + gi);
        }
        __syncthreads();

        uint32_t ah[2][4], al[2][4];
#pragma unroll
        for (int kk = 0; kk < 2; kk++) {
            ldsm4(ah[kk], sb + PJ_XH + mrow * PJ_XPITCH + kk * 32 + akb);
            ldsm4(al[kk], sb + PJ_XL + mrow * PJ_XPITCH + kk * 32 + akb);
        }
#pragma unroll
        for (int t = 0; t < 3; t++) {
#pragma unroll
            for (int j = 0; j < 8; j++) {
                uint32_t bh[4], bl[4];
                ldsm4t(bh, sb + PJ_WH + t * PJ_WTILE + krow * PJ_WPITCH + j * 16);
                ldsm4t(bl, sb + PJ_WL + t * PJ_WTILE + krow * PJ_WPITCH + j * 16);
                float* c = acc[t][j];
                mma_bf16(c, ah[0], bh[0], bh[1]);
                mma_bf16(c, ah[1], bh[2], bh[3]);
                mma_bf16(c, ah[0], bl[0], bl[1]);
                mma_bf16(c, ah[1], bl[2], bl[3]);
                mma_bf16(c, al[0], bh[0], bh[1]);
                mma_bf16(c, al[1], bh[2], bh[3]);
            }
        }
        __syncthreads();
    }

#pragma unroll
    for (int t = 0; t < 3; t++) {
        __nv_bfloat16* dh = (t == 0) ? g_Qh : (t == 1) ? g_Kh : g_Uh;
        __nv_bfloat16* dl = (t == 0) ? g_Ql : (t == 1) ? g_Kl : g_Ul;
        const float scl = (t == 0) ? 0.18033688f : 1.0f;  // 0.125 * log2(e)
#pragma unroll
        for (int j = 0; j < 8; j++) {
            int col = j * 8 + tig * 2;
            size_t r0 = (size_t)(m0 + w * 16 + gr);
            uint32_t h, l;
            split2(acc[t][j][0] * scl, acc[t][j][1] * scl, h, l);
            *reinterpret_cast<uint32_t*>(dh + r0 * 64 + col) = h;
            *reinterpret_cast<uint32_t*>(dl + r0 * 64 + col) = l;
            split2(acc[t][j][2] * scl, acc[t][j][3] * scl, h, l);
            *reinterpret_cast<uint32_t*>(dh + (r0 + 8) * 64 + col) = h;
            *reinterpret_cast<uint32_t*>(dl + (r0 + 8) * 64 + col) = l;
        }
    }
}

// ---------------------------------------------------------------------------
// Kernel 2: FA2-style flash attention, split-KV by parity.
// grid (SEQ/64, BATCH, 2); block handles kt = parity, parity+2, ... <= qt.
// Writes UNNORMALIZED fp32 partial O and partial l; combine kernel finishes.
// ---------------------------------------------------------------------------
#define FL_PITCH 144
#define FL_TILE (64 * FL_PITCH)     // 9216
#define FL_KH 0
#define FL_KL FL_TILE
#define FL_UH (2 * FL_TILE)
#define FL_UL (3 * FL_TILE)
#define FL_SMEM (4 * FL_TILE)       // 36864

__global__ __launch_bounds__(128) void flash_kernel()
{
    extern __shared__ char sm[];
    const uint32_t sb = smem_u32(sm);
    const int tid = threadIdx.x, w = tid >> 5, lane = tid & 31;
    const int gr = lane >> 2, tig = lane & 3;
    const int qt = blockIdx.x, b = blockIdx.y, par = blockIdx.z;
    const int q0 = qt * 64;
    const size_t base = (size_t)b * SEQ;

    // stage Q (64x64 hi/lo) in K buffers, pull fragments
    for (int i = tid; i < 64 * 8; i += 128) {
        int r = i >> 3, c = i & 7;
        size_t gq = (base + q0 + r) * 64 + c * 8;
        *reinterpret_cast<uint4*>(sm + FL_KH + r * FL_PITCH + c * 16) =
            *reinterpret_cast<const uint4*>(g_Qh + gq);
        *reinterpret_cast<uint4*>(sm + FL_KL + r * FL_PITCH + c * 16) =
            *reinterpret_cast<const uint4*>(g_Ql + gq);
    }
    __syncthreads();
    uint32_t qh[4][4], ql[4][4];
    {
        const int mrow = w * 16 + (lane & 7) + ((lane >> 3) & 1) * 8;
        const int akb = (lane >> 4) * 16;
#pragma unroll
        for (int kk = 0; kk < 4; kk++) {
            ldsm4(qh[kk], sb + FL_KH + mrow * FL_PITCH + kk * 32 + akb);
            ldsm4(ql[kk], sb + FL_KL + mrow * FL_PITCH + kk * 32 + akb);
        }
    }
    __syncthreads();

    float o[8][4];
#pragma unroll
    for (int j = 0; j < 8; j++)
#pragma unroll
        for (int q = 0; q < 4; q++) o[j][q] = 0.f;
    float l0 = 0.f, l1 = 0.f;

    const int row0 = q0 + w * 16 + gr, row1 = row0 + 8;
    const int nk = qt + 1;

    for (int kt = par; kt < nk; kt += 2) {
        const int k0 = kt * 64;
        for (int i = tid; i < 64 * 8; i += 128) {
            int r = i >> 3, c = i & 7;
            size_t gk = (base + k0 + r) * 64 + c * 8;
            uint32_t d = r * FL_PITCH + c * 16;
            *reinterpret_cast<uint4*>(sm + FL_KH + d) = *reinterpret_cast<const uint4*>(g_Kh + gk);
            *reinterpret_cast<uint4*>(sm + FL_KL + d) = *reinterpret_cast<const uint4*>(g_Kl + gk);
            *reinterpret_cast<uint4*>(sm + FL_UH + d) = *reinterpret_cast<const uint4*>(g_Uh + gk);
            *reinterpret_cast<uint4*>(sm + FL_UL + d) = *reinterpret_cast<const uint4*>(g_Ul + gk);
        }
        __syncthreads();

        // S = Q K^T  (split-bf16, 3 passes)
        float s[8][4];
#pragma unroll
        for (int j = 0; j < 8; j++) {
#pragma unroll
            for (int q = 0; q < 4; q++) s[j][q] = 0.f;
            uint32_t a0 = sb + FL_KH + (j * 8 + (lane & 7)) * FL_PITCH + (lane >> 3) * 16;
            uint32_t a1 = sb + FL_KL + (j * 8 + (lane & 7)) * FL_PITCH + (lane >> 3) * 16;
            uint32_t bh[4], bh2[4], bl[4], bl2[4];
            ldsm4(bh, a0); ldsm4(bh2, a0 + 64);
            ldsm4(bl, a1); ldsm4(bl2, a1 + 64);
            float* c = s[j];
            mma_bf16(c, qh[0], bh[0], bh[1]);
            mma_bf16(c, qh[1], bh[2], bh[3]);
            mma_bf16(c, qh[2], bh2[0], bh2[1]);
            mma_bf16(c, qh[3], bh2[2], bh2[3]);
            mma_bf16(c, qh[0], bl[0], bl[1]);
            mma_bf16(c, qh[1], bl[2], bl[3]);
            mma_bf16(c, qh[2], bl2[0], bl2[1]);
            mma_bf16(c, qh[3], bl2[2], bl2[3]);
            mma_bf16(c, ql[0], bh[0], bh[1]);
            mma_bf16(c, ql[1], bh[2], bh[3]);
            mma_bf16(c, ql[2], bh2[0], bh2[1]);
            mma_bf16(c, ql[3], bh2[2], bh2[3]);
        }

        // softmax (no running max): p = exp2(s); causal mask on diagonal tile
        const bool diag = (kt == qt);
#pragma unroll
        for (int j = 0; j < 8; j++) {
            int cb = k0 + j * 8 + tig * 2;
            float p0 = ex2(s[j][0]), p1 = ex2(s[j][1]);
            float p2 = ex2(s[j][2]), p3 = ex2(s[j][3]);
            if (diag) {
                if (cb > row0) p0 = 0.f;
                if (cb + 1 > row0) p1 = 0.f;
                if (cb > row1) p2 = 0.f;
                if (cb + 1 > row1) p3 = 0.f;
            }
            s[j][0] = p0; s[j][1] = p1; s[j][2] = p2; s[j][3] = p3;
            l0 += p0 + p1;
            l1 += p2 + p3;
        }

        // P fragments (C-frag -> A-frag layout identity), hi/lo
        uint32_t ph[4][4], pl[4][4];
#pragma unroll
        for (int kk = 0; kk < 4; kk++) {
            split2(s[2 * kk][0], s[2 * kk][1], ph[kk][0], pl[kk][0]);
            split2(s[2 * kk][2], s[2 * kk][3], ph[kk][1], pl[kk][1]);
            split2(s[2 * kk + 1][0], s[2 * kk + 1][1], ph[kk][2], pl[kk][2]);
            split2(s[2 * kk + 1][2], s[2 * kk + 1][3], ph[kk][3], pl[kk][3]);
        }

        // O += P U (split-bf16, 3 passes)
#pragma unroll
        for (int jp = 0; jp < 4; jp++) {
#pragma unroll
            for (int kk = 0; kk < 4; kk++) {
                int krow = kk * 16 + ((lane >> 3) & 1) * 8 + (lane & 7);
                int nbyte = (jp * 2 + (lane >> 4)) * 16;
                uint32_t bh[4], bl[4];
                ldsm4t(bh, sb + FL_UH + krow * FL_PITCH + nbyte);
                ldsm4t(bl, sb + FL_UL + krow * FL_PITCH + nbyte);
                mma_bf16(o[2 * jp], ph[kk], bh[0], bh[1]);
                mma_bf16(o[2 * jp + 1], ph[kk], bh[2], bh[3]);
                mma_bf16(o[2 * jp], ph[kk], bl[0], bl[1]);
                mma_bf16(o[2 * jp + 1], ph[kk], bl[2], bl[3]);
                mma_bf16(o[2 * jp], pl[kk], bh[0], bh[1]);
                mma_bf16(o[2 * jp + 1], pl[kk], bh[2], bh[3]);
            }
        }
        __syncthreads();
    }

    // reduce row sums across the 4-lane quad (same rows)
    l0 += __shfl_xor_sync(0xffffffffu, l0, 1);
    l0 += __shfl_xor_sync(0xffffffffu, l0, 2);
    l1 += __shfl_xor_sync(0xffffffffu, l1, 1);
    l1 += __shfl_xor_sync(0xffffffffu, l1, 2);

    float* Op = par ? g_Op1 : g_Op0;
    float* lp = par ? g_l1 : g_l0;
    const size_t r0 = base + q0 + w * 16 + gr;
    if (tig == 0) { lp[r0] = l0; lp[r0 + 8] = l1; }
#pragma unroll
    for (int j = 0; j < 8; j++) {
        int col = j * 8 + tig * 2;
        *reinterpret_cast<float2*>(&Op[r0 * 64 + col]) = make_float2(o[j][0], o[j][1]);
        *reinterpret_cast<float2*>(&Op[(r0 + 8) * 64 + col]) = make_float2(o[j][2], o[j][3]);
    }
}

// ---------------------------------------------------------------------------
// Kernel 2b: combine split-KV partials, normalize, emit bf16 hi/lo.
// ---------------------------------------------------------------------------
__global__ __launch_bounds__(256) void combine_kernel()
{
    int i = (blockIdx.x * 256 + threadIdx.x) * 2;
    int row = i >> 6;
    float inv = 1.0f / (g_l0[row] + g_l1[row]);
    float v0 = (g_Op0[i] + g_Op1[i]) * inv;
    float v1 = (g_Op0[i + 1] + g_Op1[i + 1]) * inv;
    uint32_t h, l;
    split2(v0, v1, h, l);
    *reinterpret_cast<uint32_t*>(g_Oh + i) = h;
    *reinterpret_cast<uint32_t*>(g_Ol + i) = l;
}

// ---------------------------------------------------------------------------
// Kernel 3: out[256x128 tile] = O64 @ w_v2, warp M=32 (2 chains ILP, halved
// B-fragment redundancy). grid (EMB/128, MTOT/256), 256 threads.
// ---------------------------------------------------------------------------
#define OP_OPITCH 144
#define OP_WPITCH 272
#define OP_OH 0
#define OP_OL (256 * OP_OPITCH)            // 36864
#define OP_WH (2 * 256 * OP_OPITCH)        // 73728
#define OP_WL (OP_WH + 64 * OP_WPITCH)     // 91136
#define OP_SMEM (OP_WL + 64 * OP_WPITCH)   // 108544

__global__ __launch_bounds__(256) void outproj_kernel(float* __restrict__ out)
{
    extern __shared__ char sm[];
    const uint32_t sb = smem_u32(sm);
    const int tid = threadIdx.x, w = tid >> 5, lane = tid & 31;
    const int gr = lane >> 2, tig = lane & 3;
    const int row0 = blockIdx.y * 256, col0 = blockIdx.x * 128;

    for (int i = tid; i < 256 * 8; i += 256) {
        int r = i >> 3, c = i & 7;
        size_t gi = (size_t)(row0 + r) * 64 + c * 8;
        *reinterpret_cast<uint4*>(sm + OP_OH + r * OP_OPITCH + c * 16) =
            *reinterpret_cast<const uint4*>(g_Oh + gi);
        *reinterpret_cast<uint4*>(sm + OP_OL + r * OP_OPITCH + c * 16) =
            *reinterpret_cast<const uint4*>(g_Ol + gi);
    }
    for (int i = tid; i < 64 * 16; i += 256) {
        int r = i >> 4, c = i & 15;
        size_t gi = (size_t)r * EMB + col0 + c * 8;
        *reinterpret_cast<uint4*>(sm + OP_WH + r * OP_WPITCH + c * 16) =
            *reinterpret_cast<const uint4*>(g_W2h + gi);
        *reinterpret_cast<uint4*>(sm + OP_WL + r * OP_WPITCH + c * 16) =
            *reinterpret_cast<const uint4*>(g_W2l + gi);
    }
    __syncthreads();

    uint32_t ah[2][4][4], al[2][4][4];
    const int akb = (lane >> 4) * 16;
#pragma unroll
    for (int m = 0; m < 2; m++) {
        const int mrow = w * 32 + m * 16 + (lane & 7) + ((lane >> 3) & 1) * 8;
#pragma unroll
        for (int kk = 0; kk < 4; kk++) {
            ldsm4(ah[m][kk], sb + OP_OH + mrow * OP_OPITCH + kk * 32 + akb);
            ldsm4(al[m][kk], sb + OP_OL + mrow * OP_OPITCH + kk * 32 + akb);
        }
    }

#pragma unroll
    for (int j = 0; j < 16; j++) {
        float c[2][4];
#pragma unroll
        for (int m = 0; m < 2; m++)
#pragma unroll
            for (int q = 0; q < 4; q++) c[m][q] = 0.f;
#pragma unroll
        for (int kp = 0; kp < 2; kp++) {
            int krow = kp * 32 + (lane >> 4) * 16 + ((lane >> 3) & 1) * 8 + (lane & 7);
            uint32_t bh[4], bl[4];
            ldsm4t(bh, sb + OP_WH + krow * OP_WPITCH + j * 16);
            ldsm4t(bl, sb + OP_WL + krow * OP_WPITCH + j * 16);
#pragma unroll
            for (int m = 0; m < 2; m++) {
                mma_bf16(c[m], ah[m][2 * kp], bh[0], bh[1]);
                mma_bf16(c[m], ah[m][2 * kp + 1], bh[2], bh[3]);
                mma_bf16(c[m], ah[m][2 * kp], bl[0], bl[1]);
                mma_bf16(c[m], ah[m][2 * kp + 1], bl[2], bl[3]);
                mma_bf16(c[m], al[m][2 * kp], bh[0], bh[1]);
                mma_bf16(c[m], al[m][2 * kp + 1], bh[2], bh[3]);
            }
        }
        int col = col0 + j * 8 + tig * 2;
#pragma unroll
        for (int m = 0; m < 2; m++) {
            int r = row0 + w * 32 + m * 16 + gr;
            *reinterpret_cast<float2*>(&out[(size_t)r * EMB + col]) =
                make_float2(c[m][0], c[m][1]);
            *reinterpret_cast<float2*>(&out[(size_t)(r + 8) * EMB + col]) =
                make_float2(c[m][2], c[m][3]);
        }
    }
}

// ---------------------------------------------------------------------------
extern "C" void kernel_launch(void* const* d_in, const int* in_sizes, int n_in,
                              void* d_out, int out_size)
{
    const float* x    = (const float*)d_in[0];
    const float* w_q  = (const float*)d_in[1];
    const float* w_k  = (const float*)d_in[2];
    const float* w_v1 = (const float*)d_in[3];
    const float* w_v2 = (const float*)d_in[4];
    float* out = (float*)d_out;
    (void)in_sizes; (void)n_in; (void)out_size;

    cudaFuncSetAttribute(proj_kernel, cudaFuncAttributeMaxDynamicSharedMemorySize, PJ_SMEM);
    cudaFuncSetAttribute(flash_kernel, cudaFuncAttributeMaxDynamicSharedMemorySize, FL_SMEM);
    cudaFuncSetAttribute(outproj_kernel, cudaFuncAttributeMaxDynamicSharedMemorySize, OP_SMEM);

    convw_kernel<<<512, 256>>>(w_q, w_k, w_v1, w_v2);
    proj_kernel<<<MTOT / 64, 128, PJ_SMEM>>>(x);
    flash_kernel<<<dim3(SEQ / 64, BATCH, 2), 128, FL_SMEM>>>();
    combine_kernel<<<MTOT * DHEAD / 512, 256>>>();
    outproj_kernel<<<dim3(EMB / 128, MTOT / 256), 256, OP_SMEM>>>(out);
}

// round 5
// speedup vs baseline: 4.6172x; 1.0767x over previous
#include <cuda_runtime.h>
#include <cuda_bf16.h>
#include <math.h>
#include <stdint.h>

#define EMB 1024
#define DHEAD 64
#define BATCH 8
#define SEQ 2048
#define MTOT (BATCH * SEQ)   // 16384

// ---------------------------------------------------------------------------
// Scratch (__device__ globals; no cudaMalloc allowed)
// ---------------------------------------------------------------------------
__device__ __nv_bfloat16 g_Qh[MTOT * DHEAD], g_Ql[MTOT * DHEAD]; // pre-scaled 0.125*log2e
__device__ __nv_bfloat16 g_Kh[MTOT * DHEAD], g_Kl[MTOT * DHEAD];
__device__ __nv_bfloat16 g_Uh[MTOT * DHEAD], g_Ul[MTOT * DHEAD]; // U = x@w_v1
__device__ __nv_bfloat16 g_Wh[3 * EMB * DHEAD], g_Wl[3 * EMB * DHEAD]; // wq|wk|wv1
__device__ __nv_bfloat16 g_W2h[DHEAD * EMB], g_W2l[DHEAD * EMB];
// split-KV partials (unnormalized)
__device__ float g_Op0[MTOT * DHEAD], g_Op1[MTOT * DHEAD];
__device__ float g_l0[MTOT], g_l1[MTOT];

// ---------------------------------------------------------------------------
// Helpers
// ---------------------------------------------------------------------------
__device__ __forceinline__ uint32_t smem_u32(const void* p) {
    uint32_t a;
    asm("{ .reg .u64 t; cvta.to.shared.u64 t, %1; cvt.u32.u64 %0, t; }" : "=r"(a) : "l"(p));
    return a;
}
__device__ __forceinline__ void ldsm4(uint32_t* r, uint32_t a) {
    asm volatile("ldmatrix.sync.aligned.m8n8.x4.shared.b16 {%0,%1,%2,%3}, [%4];"
                 : "=r"(r[0]), "=r"(r[1]), "=r"(r[2]), "=r"(r[3]) : "r"(a));
}
__device__ __forceinline__ void ldsm4t(uint32_t* r, uint32_t a) {
    asm volatile("ldmatrix.sync.aligned.m8n8.x4.trans.shared.b16 {%0,%1,%2,%3}, [%4];"
                 : "=r"(r[0]), "=r"(r[1]), "=r"(r[2]), "=r"(r[3]) : "r"(a));
}
__device__ __forceinline__ void mma_bf16(float* c, const uint32_t* a, uint32_t b0, uint32_t b1) {
    asm volatile("mma.sync.aligned.m16n8k16.row.col.f32.bf16.bf16.f32 "
                 "{%0,%1,%2,%3}, {%4,%5,%6,%7}, {%8,%9}, {%0,%1,%2,%3};"
                 : "+f"(c[0]), "+f"(c[1]), "+f"(c[2]), "+f"(c[3])
                 : "r"(a[0]), "r"(a[1]), "r"(a[2]), "r"(a[3]), "r"(b0), "r"(b1));
}
__device__ __forceinline__ uint32_t packbf(float v0, float v1) {
    uint32_t r;
    asm("cvt.rn.bf16x2.f32 %0, %1, %2;" : "=r"(r) : "f"(v1), "f"(v0));
    return r;
}
__device__ __forceinline__ void split2(float v0, float v1, uint32_t& hi, uint32_t& lo) {
    hi = packbf(v0, v1);
    float h0 = __uint_as_float(hi << 16);
    float h1 = __uint_as_float(hi & 0xFFFF0000u);
    lo = packbf(v0 - h0, v1 - h1);
}
__device__ __forceinline__ float ex2(float x) {
    float r;
    asm("ex2.approx.ftz.f32 %0, %1;" : "=f"(r) : "f"(x));
    return r;
}
__device__ __forceinline__ void cp16(uint32_t s, const void* g) {
    asm volatile("cp.async.cg.shared.global [%0], [%1], 16;" :: "r"(s), "l"(g));
}
#define CP_COMMIT() asm volatile("cp.async.commit_group;" ::: "memory")
#define CP_WAIT1()  asm volatile("cp.async.wait_group 1;" ::: "memory")

// ---------------------------------------------------------------------------
// Kernel 0: convert weights to bf16 hi/lo
// ---------------------------------------------------------------------------
__global__ __launch_bounds__(256) void convw_kernel(
    const float* __restrict__ wq, const float* __restrict__ wk,
    const float* __restrict__ wv1, const float* __restrict__ wv2)
{
    int p = (blockIdx.x * 256 + threadIdx.x) * 2;
    float v0, v1;
    __nv_bfloat16 *dh, *dl;
    int off;
    if (p < 3 * EMB * DHEAD) {
        const float* src = (p < EMB * DHEAD) ? wq : (p < 2 * EMB * DHEAD) ? wk : wv1;
        int e = p & (EMB * DHEAD - 1);
        v0 = src[e]; v1 = src[e + 1];
        dh = g_Wh; dl = g_Wl; off = p;
    } else {
        int e = p - 3 * EMB * DHEAD;
        v0 = wv2[e]; v1 = wv2[e + 1];
        dh = g_W2h; dl = g_W2l; off = e;
    }
    uint32_t hi, lo;
    split2(v0, v1, hi, lo);
    *reinterpret_cast<uint32_t*>(dh + off) = hi;
    *reinterpret_cast<uint32_t*>(dl + off) = lo;
}

// ---------------------------------------------------------------------------
// Kernel 1: fused projections via mma.sync. 64-row tiles, 128 threads,
// grid = 256 blocks. Weights cp.async double-buffered; x reg-pipelined.
// ---------------------------------------------------------------------------
#define PJ_XPITCH 80
#define PJ_WPITCH 144
#define PJ_XH 0
#define PJ_XL (64 * PJ_XPITCH)            // 5120
#define PJ_WBASE (2 * 64 * PJ_XPITCH)     // 10240
#define PJ_WTILE (32 * PJ_WPITCH)         // 4608
#define PJ_WSET (3 * PJ_WTILE)            // 13824 (3 weight tiles, hi)
#define PJ_WBUF (2 * PJ_WSET)             // 27648 (hi + lo)
#define PJ_SMEM (PJ_WBASE + 2 * PJ_WBUF)  // 65536

__global__ __launch_bounds__(128) void proj_kernel(const float* __restrict__ x)
{
    extern __shared__ char sm[];
    const uint32_t sb = smem_u32(sm);
    const int tid = threadIdx.x, w = tid >> 5, lane = tid & 31;
    const int gr = lane >> 2, tig = lane & 3;
    const int m0 = blockIdx.x * 64;

    float acc[3][8][4];
#pragma unroll
    for (int t = 0; t < 3; t++)
#pragma unroll
        for (int j = 0; j < 8; j++)
#pragma unroll
            for (int q = 0; q < 4; q++) acc[t][j][q] = 0.f;

    const int mrow = w * 16 + (lane & 7) + ((lane >> 3) & 1) * 8;
    const int akb = (lane >> 4) * 16;
    const int krow = (lane >> 4) * 16 + ((lane >> 3) & 1) * 8 + (lane & 7);

    // weight prefetch: 768 16B chunks (hi) + 768 (lo) per k-chunk
    auto wload = [&](int k0, uint32_t bufbase) {
#pragma unroll
        for (int i = tid; i < 768; i += 128) {
            int t = i >> 8, r = (i >> 3) & 31, c = i & 7;
            size_t gi = (size_t)t * EMB * 64 + (size_t)(k0 + r) * 64 + c * 8;
            uint32_t d = bufbase + t * PJ_WTILE + r * PJ_WPITCH + c * 16;
            cp16(sb + d, g_Wh + gi);
            cp16(sb + d + PJ_WSET, g_Wl + gi);
        }
    };

    // preload x regs for iter 0 (each thread 4 float4)
    float4 xv[4], xn[4];
#pragma unroll
    for (int j = 0; j < 4; j++) {
        int i = tid + j * 128, r = i >> 3, c = (i & 7) * 4;
        xv[j] = *reinterpret_cast<const float4*>(&x[(size_t)(m0 + r) * EMB + c]);
    }
    wload(0, PJ_WBASE);
    CP_COMMIT();

    for (int it = 0; it < 32; it++) {
        const int k0 = it * 32;
        const uint32_t wb = PJ_WBASE + (uint32_t)(it & 1) * PJ_WBUF;
        if (it < 31) wload(k0 + 32, PJ_WBASE + (uint32_t)((it + 1) & 1) * PJ_WBUF);
        CP_COMMIT();
        if (it < 31) {
#pragma unroll
            for (int j = 0; j < 4; j++) {
                int i = tid + j * 128, r = i >> 3, c = (i & 7) * 4;
                xn[j] = *reinterpret_cast<const float4*>(&x[(size_t)(m0 + r) * EMB + k0 + 32 + c]);
            }
        }
        // split + store x regs into smem operand buffers
#pragma unroll
        for (int j = 0; j < 4; j++) {
            int i = tid + j * 128, r = i >> 3, c = (i & 7) * 4;
            uint32_t h0, l0, h1, l1;
            split2(xv[j].x, xv[j].y, h0, l0);
            split2(xv[j].z, xv[j].w, h1, l1);
            uint32_t* ph = reinterpret_cast<uint32_t*>(sm + PJ_XH + r * PJ_XPITCH + c * 2);
            ph[0] = h0; ph[1] = h1;
            uint32_t* pl = reinterpret_cast<uint32_t*>(sm + PJ_XL + r * PJ_XPITCH + c * 2);
            pl[0] = l0; pl[1] = l1;
        }
        CP_WAIT1();
        __syncthreads();

        uint32_t ah[2][4], al[2][4];
#pragma unroll
        for (int kk = 0; kk < 2; kk++) {
            ldsm4(ah[kk], sb + PJ_XH + mrow * PJ_XPITCH + kk * 32 + akb);
            ldsm4(al[kk], sb + PJ_XL + mrow * PJ_XPITCH + kk * 32 + akb);
        }
#pragma unroll
        for (int t = 0; t < 3; t++) {
#pragma unroll
            for (int j = 0; j < 8; j++) {
                uint32_t bh[4], bl[4];
                ldsm4t(bh, sb + wb + t * PJ_WTILE + krow * PJ_WPITCH + j * 16);
                ldsm4t(bl, sb + wb + PJ_WSET + t * PJ_WTILE + krow * PJ_WPITCH + j * 16);
                float* c = acc[t][j];
                mma_bf16(c, ah[0], bh[0], bh[1]);
                mma_bf16(c, ah[1], bh[2], bh[3]);
                mma_bf16(c, ah[0], bl[0], bl[1]);
                mma_bf16(c, ah[1], bl[2], bl[3]);
                mma_bf16(c, al[0], bh[0], bh[1]);
                mma_bf16(c, al[1], bh[2], bh[3]);
            }
        }
        __syncthreads();
#pragma unroll
        for (int j = 0; j < 4; j++) xv[j] = xn[j];
    }

#pragma unroll
    for (int t = 0; t < 3; t++) {
        __nv_bfloat16* dh = (t == 0) ? g_Qh : (t == 1) ? g_Kh : g_Uh;
        __nv_bfloat16* dl = (t == 0) ? g_Ql : (t == 1) ? g_Kl : g_Ul;
        const float scl = (t == 0) ? 0.18033688f : 1.0f;  // 0.125 * log2(e)
#pragma unroll
        for (int j = 0; j < 8; j++) {
            int col = j * 8 + tig * 2;
            size_t r0 = (size_t)(m0 + w * 16 + gr);
            uint32_t h, l;
            split2(acc[t][j][0] * scl, acc[t][j][1] * scl, h, l);
            *reinterpret_cast<uint32_t*>(dh + r0 * 64 + col) = h;
            *reinterpret_cast<uint32_t*>(dl + r0 * 64 + col) = l;
            split2(acc[t][j][2] * scl, acc[t][j][3] * scl, h, l);
            *reinterpret_cast<uint32_t*>(dh + (r0 + 8) * 64 + col) = h;
            *reinterpret_cast<uint32_t*>(dl + (r0 + 8) * 64 + col) = l;
        }
    }
}

// ---------------------------------------------------------------------------
// Kernel 2: FA2 flash attention, split-KV by parity, cp.async double-buffered.
// grid (SEQ/64, BATCH, 2); 128 threads.
// ---------------------------------------------------------------------------
#define FL_PITCH 144
#define FL_TILE (64 * FL_PITCH)       // 9216
#define FL_STAGE (4 * FL_TILE)        // 36864 (KH,KL,UH,UL)
#define FL_SMEM (2 * FL_STAGE)        // 73728

__global__ __launch_bounds__(128) void flash_kernel()
{
    extern __shared__ char sm[];
    const uint32_t sb = smem_u32(sm);
    const int tid = threadIdx.x, w = tid >> 5, lane = tid & 31;
    const int gr = lane >> 2, tig = lane & 3;
    const int qt = blockIdx.x, b = blockIdx.y, par = blockIdx.z;
    const int q0 = qt * 64;
    const size_t base = (size_t)b * SEQ;

    // stage Q (64x64 hi/lo) into stage0 KH/KL areas, pull fragments
    for (int i = tid; i < 64 * 8; i += 128) {
        int r = i >> 3, c = i & 7;
        size_t gq = (base + q0 + r) * 64 + c * 8;
        *reinterpret_cast<uint4*>(sm + r * FL_PITCH + c * 16) =
            *reinterpret_cast<const uint4*>(g_Qh + gq);
        *reinterpret_cast<uint4*>(sm + FL_TILE + r * FL_PITCH + c * 16) =
            *reinterpret_cast<const uint4*>(g_Ql + gq);
    }
    __syncthreads();
    uint32_t qh[4][4], ql[4][4];
    {
        const int mrow = w * 16 + (lane & 7) + ((lane >> 3) & 1) * 8;
        const int akb = (lane >> 4) * 16;
#pragma unroll
        for (int kk = 0; kk < 4; kk++) {
            ldsm4(qh[kk], sb + mrow * FL_PITCH + kk * 32 + akb);
            ldsm4(ql[kk], sb + FL_TILE + mrow * FL_PITCH + kk * 32 + akb);
        }
    }
    __syncthreads();

    auto load_tile = [&](int kt, uint32_t bb) {
        const int k0 = kt * 64;
#pragma unroll
        for (int i = tid; i < 64 * 8; i += 128) {
            int r = i >> 3, c = i & 7;
            uint32_t d = bb + r * FL_PITCH + c * 16;
            size_t gk = (base + k0 + r) * 64 + c * 8;
            cp16(sb + d, g_Kh + gk);
            cp16(sb + d + FL_TILE, g_Kl + gk);
            cp16(sb + d + 2 * FL_TILE, g_Uh + gk);
            cp16(sb + d + 3 * FL_TILE, g_Ul + gk);
        }
    };

    float o[8][4];
#pragma unroll
    for (int j = 0; j < 8; j++)
#pragma unroll
        for (int q = 0; q < 4; q++) o[j][q] = 0.f;
    float l0 = 0.f, l1 = 0.f;

    const int row0 = q0 + w * 16 + gr, row1 = row0 + 8;

    if (par <= qt) load_tile(par, 0);
    CP_COMMIT();

    int it = 0;
    for (int kt = par; kt <= qt; kt += 2, it++) {
        const int k0 = kt * 64;
        const uint32_t bb = (uint32_t)(it & 1) * FL_STAGE;
        if (kt + 2 <= qt) load_tile(kt + 2, (uint32_t)((it + 1) & 1) * FL_STAGE);
        CP_COMMIT();
        CP_WAIT1();
        __syncthreads();

        // S = Q K^T  (split-bf16, 3 passes)
        float s[8][4];
#pragma unroll
        for (int j = 0; j < 8; j++) {
#pragma unroll
            for (int q = 0; q < 4; q++) s[j][q] = 0.f;
            uint32_t a0 = sb + bb + (j * 8 + (lane & 7)) * FL_PITCH + (lane >> 3) * 16;
            uint32_t a1 = a0 + FL_TILE;
            uint32_t bh[4], bh2[4], bl[4], bl2[4];
            ldsm4(bh, a0); ldsm4(bh2, a0 + 64);
            ldsm4(bl, a1); ldsm4(bl2, a1 + 64);
            float* c = s[j];
            mma_bf16(c, qh[0], bh[0], bh[1]);
            mma_bf16(c, qh[1], bh[2], bh[3]);
            mma_bf16(c, qh[2], bh2[0], bh2[1]);
            mma_bf16(c, qh[3], bh2[2], bh2[3]);
            mma_bf16(c, qh[0], bl[0], bl[1]);
            mma_bf16(c, qh[1], bl[2], bl[3]);
            mma_bf16(c, qh[2], bl2[0], bl2[1]);
            mma_bf16(c, qh[3], bl2[2], bl2[3]);
            mma_bf16(c, ql[0], bh[0], bh[1]);
            mma_bf16(c, ql[1], bh[2], bh[3]);
            mma_bf16(c, ql[2], bh2[0], bh2[1]);
            mma_bf16(c, ql[3], bh2[2], bh2[3]);
        }

        // softmax: p = exp2(s); causal mask only on diagonal tile
        const bool diag = (kt == qt);
#pragma unroll
        for (int j = 0; j < 8; j++) {
            int cb = k0 + j * 8 + tig * 2;
            float p0 = ex2(s[j][0]), p1 = ex2(s[j][1]);
            float p2 = ex2(s[j][2]), p3 = ex2(s[j][3]);
            if (diag) {
                if (cb > row0) p0 = 0.f;
                if (cb + 1 > row0) p1 = 0.f;
                if (cb > row1) p2 = 0.f;
                if (cb + 1 > row1) p3 = 0.f;
            }
            s[j][0] = p0; s[j][1] = p1; s[j][2] = p2; s[j][3] = p3;
            l0 += p0 + p1;
            l1 += p2 + p3;
        }

        // P fragments (C-frag -> A-frag identity), hi/lo
        uint32_t ph[4][4], pl[4][4];
#pragma unroll
        for (int kk = 0; kk < 4; kk++) {
            split2(s[2 * kk][0], s[2 * kk][1], ph[kk][0], pl[kk][0]);
            split2(s[2 * kk][2], s[2 * kk][3], ph[kk][1], pl[kk][1]);
            split2(s[2 * kk + 1][0], s[2 * kk + 1][1], ph[kk][2], pl[kk][2]);
            split2(s[2 * kk + 1][2], s[2 * kk + 1][3], ph[kk][3], pl[kk][3]);
        }

        // O += P U (split-bf16, 3 passes)
#pragma unroll
        for (int jp = 0; jp < 4; jp++) {
#pragma unroll
            for (int kk = 0; kk < 4; kk++) {
                int krow = kk * 16 + ((lane >> 3) & 1) * 8 + (lane & 7);
                int nbyte = (jp * 2 + (lane >> 4)) * 16;
                uint32_t bh[4], bl[4];
                ldsm4t(bh, sb + bb + 2 * FL_TILE + krow * FL_PITCH + nbyte);
                ldsm4t(bl, sb + bb + 3 * FL_TILE + krow * FL_PITCH + nbyte);
                mma_bf16(o[2 * jp], ph[kk], bh[0], bh[1]);
                mma_bf16(o[2 * jp + 1], ph[kk], bh[2], bh[3]);
                mma_bf16(o[2 * jp], ph[kk], bl[0], bl[1]);
                mma_bf16(o[2 * jp + 1], ph[kk], bl[2], bl[3]);
                mma_bf16(o[2 * jp], pl[kk], bh[0], bh[1]);
                mma_bf16(o[2 * jp + 1], pl[kk], bh[2], bh[3]);
            }
        }
        __syncthreads();
    }

    // reduce row sums across the 4-lane quad (same rows)
    l0 += __shfl_xor_sync(0xffffffffu, l0, 1);
    l0 += __shfl_xor_sync(0xffffffffu, l0, 2);
    l1 += __shfl_xor_sync(0xffffffffu, l1, 1);
    l1 += __shfl_xor_sync(0xffffffffu, l1, 2);

    float* Op = par ? g_Op1 : g_Op0;
    float* lp = par ? g_l1 : g_l0;
    const size_t r0 = base + q0 + w * 16 + gr;
    if (tig == 0) { lp[r0] = l0; lp[r0 + 8] = l1; }
#pragma unroll
    for (int j = 0; j < 8; j++) {
        int col = j * 8 + tig * 2;
        *reinterpret_cast<float2*>(&Op[r0 * 64 + col]) = make_float2(o[j][0], o[j][1]);
        *reinterpret_cast<float2*>(&Op[(r0 + 8) * 64 + col]) = make_float2(o[j][2], o[j][3]);
    }
}

// ---------------------------------------------------------------------------
// Kernel 3: out[256x128] = normalize(Op0+Op1) @ w_v2 (combine fused in).
// ---------------------------------------------------------------------------
#define OP_OPITCH 144
#define OP_WPITCH 272
#define OP_OH 0
#define OP_OL (256 * OP_OPITCH)            // 36864
#define OP_WH (2 * 256 * OP_OPITCH)        // 73728
#define OP_WL (OP_WH + 64 * OP_WPITCH)     // 91136
#define OP_SMEM (OP_WL + 64 * OP_WPITCH)   // 108544

__global__ __launch_bounds__(256) void outproj_kernel(float* __restrict__ out)
{
    extern __shared__ char sm[];
    const uint32_t sb = smem_u32(sm);
    const int tid = threadIdx.x, w = tid >> 5, lane = tid & 31;
    const int gr = lane >> 2, tig = lane & 3;
    const int row0 = blockIdx.y * 256, col0 = blockIdx.x * 128;

    // A operand: combine split-KV partials, normalize, split to bf16 hi/lo
    for (int i = tid; i < 256 * 16; i += 256) {
        int r = i >> 4, cc = (i & 15) * 4;
        float inv = 1.0f / (g_l0[row0 + r] + g_l1[row0 + r]);
        size_t gi = (size_t)(row0 + r) * 64 + cc;
        float4 a = *reinterpret_cast<const float4*>(g_Op0 + gi);
        float4 c4 = *reinterpret_cast<const float4*>(g_Op1 + gi);
        float v0 = (a.x + c4.x) * inv, v1 = (a.y + c4.y) * inv;
        float v2 = (a.z + c4.z) * inv, v3 = (a.w + c4.w) * inv;
        uint32_t h0, l0_, h1, l1_;
        split2(v0, v1, h0, l0_);
        split2(v2, v3, h1, l1_);
        uint32_t* ph = reinterpret_cast<uint32_t*>(sm + OP_OH + r * OP_OPITCH + cc * 2);
        ph[0] = h0; ph[1] = h1;
        uint32_t* pl = reinterpret_cast<uint32_t*>(sm + OP_OL + r * OP_OPITCH + cc * 2);
        pl[0] = l0_; pl[1] = l1_;
    }
    for (int i = tid; i < 64 * 16; i += 256) {
        int r = i >> 4, c = i & 15;
        size_t gi = (size_t)r * EMB + col0 + c * 8;
        *reinterpret_cast<uint4*>(sm + OP_WH + r * OP_WPITCH + c * 16) =
            *reinterpret_cast<const uint4*>(g_W2h + gi);
        *reinterpret_cast<uint4*>(sm + OP_WL + r * OP_WPITCH + c * 16) =
            *reinterpret_cast<const uint4*>(g_W2l + gi);
    }
    __syncthreads();

    uint32_t ah[2][4][4], al[2][4][4];
    const int akb = (lane >> 4) * 16;
#pragma unroll
    for (int m = 0; m < 2; m++) {
        const int mrow = w * 32 + m * 16 + (lane & 7) + ((lane >> 3) & 1) * 8;
#pragma unroll
        for (int kk = 0; kk < 4; kk++) {
            ldsm4(ah[m][kk], sb + OP_OH + mrow * OP_OPITCH + kk * 32 + akb);
            ldsm4(al[m][kk], sb + OP_OL + mrow * OP_OPITCH + kk * 32 + akb);
        }
    }

#pragma unroll
    for (int j = 0; j < 16; j++) {
        float c[2][4];
#pragma unroll
        for (int m = 0; m < 2; m++)
#pragma unroll
            for (int q = 0; q < 4; q++) c[m][q] = 0.f;
#pragma unroll
        for (int kp = 0; kp < 2; kp++) {
            int krow = kp * 32 + (lane >> 4) * 16 + ((lane >> 3) & 1) * 8 + (lane & 7);
            uint32_t bh[4], bl[4];
            ldsm4t(bh, sb + OP_WH + krow * OP_WPITCH + j * 16);
            ldsm4t(bl, sb + OP_WL + krow * OP_WPITCH + j * 16);
#pragma unroll
            for (int m = 0; m < 2; m++) {
                mma_bf16(c[m], ah[m][2 * kp], bh[0], bh[1]);
                mma_bf16(c[m], ah[m][2 * kp + 1], bh[2], bh[3]);
                mma_bf16(c[m], ah[m][2 * kp], bl[0], bl[1]);
                mma_bf16(c[m], ah[m][2 * kp + 1], bl[2], bl[3]);
                mma_bf16(c[m], al[m][2 * kp], bh[0], bh[1]);
                mma_bf16(c[m], al[m][2 * kp + 1], bh[2], bh[3]);
            }
        }
        int col = col0 + j * 8 + tig * 2;
#pragma unroll
        for (int m = 0; m < 2; m++) {
            int r = row0 + w * 32 + m * 16 + gr;
            *reinterpret_cast<float2*>(&out[(size_t)r * EMB + col]) =
                make_float2(c[m][0], c[m][1]);
            *reinterpret_cast<float2*>(&out[(size_t)(r + 8) * EMB + col]) =
                make_float2(c[m][2], c[m][3]);
        }
    }
}

// ---------------------------------------------------------------------------
extern "C" void kernel_launch(void* const* d_in, const int* in_sizes, int n_in,
                              void* d_out, int out_size)
{
    const float* x    = (const float*)d_in[0];
    const float* w_q  = (const float*)d_in[1];
    const float* w_k  = (const float*)d_in[2];
    const float* w_v1 = (const float*)d_in[3];
    const float* w_v2 = (const float*)d_in[4];
    float* out = (float*)d_out;
    (void)in_sizes; (void)n_in; (void)out_size;

    cudaFuncSetAttribute(proj_kernel, cudaFuncAttributeMaxDynamicSharedMemorySize, PJ_SMEM);
    cudaFuncSetAttribute(flash_kernel, cudaFuncAttributeMaxDynamicSharedMemorySize, FL_SMEM);
    cudaFuncSetAttribute(outproj_kernel, cudaFuncAttributeMaxDynamicSharedMemorySize, OP_SMEM);

    convw_kernel<<<512, 256>>>(w_q, w_k, w_v1, w_v2);
    proj_kernel<<<MTOT / 64, 128, PJ_SMEM>>>(x);
    flash_kernel<<<dim3(SEQ / 64, BATCH, 2), 128, FL_SMEM>>>();
    outproj_kernel<<<dim3(EMB / 128, MTOT / 256), 256, OP_SMEM>>>(out);
}

// round 6
// speedup vs baseline: 4.8168x; 1.0432x over previous
#include <cuda_runtime.h>
#include <cuda_bf16.h>
#include <math.h>
#include <stdint.h>

#define EMB 1024
#define DHEAD 64
#define BATCH 8
#define SEQ 2048
#define MTOT (BATCH * SEQ)   // 16384
#define NSPLIT 4

// ---------------------------------------------------------------------------
// Scratch (__device__ globals; no cudaMalloc allowed)
// ---------------------------------------------------------------------------
__device__ __nv_bfloat16 g_Qh[MTOT * DHEAD], g_Ql[MTOT * DHEAD]; // pre-scaled 0.125*log2e
__device__ __nv_bfloat16 g_Kh[MTOT * DHEAD], g_Kl[MTOT * DHEAD];
__device__ __nv_bfloat16 g_Uh[MTOT * DHEAD], g_Ul[MTOT * DHEAD]; // U = x@w_v1
__device__ __nv_bfloat16 g_Oh[MTOT * DHEAD], g_Ol[MTOT * DHEAD]; // attn out (pre w_v2)
__device__ __nv_bfloat16 g_Wh[3 * EMB * DHEAD], g_Wl[3 * EMB * DHEAD]; // wq|wk|wv1
__device__ __nv_bfloat16 g_W2h[DHEAD * EMB], g_W2l[DHEAD * EMB];
// split-KV partials (unnormalized)
__device__ float g_Op[NSPLIT][MTOT * DHEAD];
__device__ float g_l[NSPLIT][MTOT];

// ---------------------------------------------------------------------------
// Helpers
// ---------------------------------------------------------------------------
__device__ __forceinline__ uint32_t smem_u32(const void* p) {
    uint32_t a;
    asm("{ .reg .u64 t; cvta.to.shared.u64 t, %1; cvt.u32.u64 %0, t; }" : "=r"(a) : "l"(p));
    return a;
}
__device__ __forceinline__ void ldsm4(uint32_t* r, uint32_t a) {
    asm volatile("ldmatrix.sync.aligned.m8n8.x4.shared.b16 {%0,%1,%2,%3}, [%4];"
                 : "=r"(r[0]), "=r"(r[1]), "=r"(r[2]), "=r"(r[3]) : "r"(a));
}
__device__ __forceinline__ void ldsm4t(uint32_t* r, uint32_t a) {
    asm volatile("ldmatrix.sync.aligned.m8n8.x4.trans.shared.b16 {%0,%1,%2,%3}, [%4];"
                 : "=r"(r[0]), "=r"(r[1]), "=r"(r[2]), "=r"(r[3]) : "r"(a));
}
__device__ __forceinline__ void mma_bf16(float* c, const uint32_t* a, uint32_t b0, uint32_t b1) {
    asm volatile("mma.sync.aligned.m16n8k16.row.col.f32.bf16.bf16.f32 "
                 "{%0,%1,%2,%3}, {%4,%5,%6,%7}, {%8,%9}, {%0,%1,%2,%3};"
                 : "+f"(c[0]), "+f"(c[1]), "+f"(c[2]), "+f"(c[3])
                 : "r"(a[0]), "r"(a[1]), "r"(a[2]), "r"(a[3]), "r"(b0), "r"(b1));
}
__device__ __forceinline__ uint32_t packbf(float v0, float v1) {
    uint32_t r;
    asm("cvt.rn.bf16x2.f32 %0, %1, %2;" : "=r"(r) : "f"(v1), "f"(v0));
    return r;
}
__device__ __forceinline__ void split2(float v0, float v1, uint32_t& hi, uint32_t& lo) {
    hi = packbf(v0, v1);
    float h0 = __uint_as_float(hi << 16);
    float h1 = __uint_as_float(hi & 0xFFFF0000u);
    lo = packbf(v0 - h0, v1 - h1);
}
__device__ __forceinline__ float ex2(float x) {
    float r;
    asm("ex2.approx.ftz.f32 %0, %1;" : "=f"(r) : "f"(x));
    return r;
}
__device__ __forceinline__ void cp16(uint32_t s, const void* g) {
    asm volatile("cp.async.cg.shared.global [%0], [%1], 16;" :: "r"(s), "l"(g));
}
#define CP_COMMIT() asm volatile("cp.async.commit_group;" ::: "memory")
#define CP_WAIT1()  asm volatile("cp.async.wait_group 1;" ::: "memory")

// ---------------------------------------------------------------------------
// Kernel 0: convert weights to bf16 hi/lo
// ---------------------------------------------------------------------------
__global__ __launch_bounds__(256) void convw_kernel(
    const float* __restrict__ wq, const float* __restrict__ wk,
    const float* __restrict__ wv1, const float* __restrict__ wv2)
{
    int p = (blockIdx.x * 256 + threadIdx.x) * 2;
    float v0, v1;
    __nv_bfloat16 *dh, *dl;
    int off;
    if (p < 3 * EMB * DHEAD) {
        const float* src = (p < EMB * DHEAD) ? wq : (p < 2 * EMB * DHEAD) ? wk : wv1;
        int e = p & (EMB * DHEAD - 1);
        v0 = src[e]; v1 = src[e + 1];
        dh = g_Wh; dl = g_Wl; off = p;
    } else {
        int e = p - 3 * EMB * DHEAD;
        v0 = wv2[e]; v1 = wv2[e + 1];
        dh = g_W2h; dl = g_W2l; off = e;
    }
    uint32_t hi, lo;
    split2(v0, v1, hi, lo);
    *reinterpret_cast<uint32_t*>(dh + off) = hi;
    *reinterpret_cast<uint32_t*>(dl + off) = lo;
}

// ---------------------------------------------------------------------------
// Kernel 1: fused projections via mma.sync. 64-row tiles, 128 threads,
// grid = 256 blocks. Weights cp.async double-buffered; x reg-pipelined.
// ---------------------------------------------------------------------------
#define PJ_XPITCH 80
#define PJ_WPITCH 144
#define PJ_XH 0
#define PJ_XL (64 * PJ_XPITCH)            // 5120
#define PJ_WBASE (2 * 64 * PJ_XPITCH)     // 10240
#define PJ_WTILE (32 * PJ_WPITCH)         // 4608
#define PJ_WSET (3 * PJ_WTILE)            // 13824
#define PJ_WBUF (2 * PJ_WSET)             // 27648
#define PJ_SMEM (PJ_WBASE + 2 * PJ_WBUF)  // 65536

__global__ __launch_bounds__(128) void proj_kernel(const float* __restrict__ x)
{
    extern __shared__ char sm[];
    const uint32_t sb = smem_u32(sm);
    const int tid = threadIdx.x, w = tid >> 5, lane = tid & 31;
    const int gr = lane >> 2, tig = lane & 3;
    const int m0 = blockIdx.x * 64;

    float acc[3][8][4];
#pragma unroll
    for (int t = 0; t < 3; t++)
#pragma unroll
        for (int j = 0; j < 8; j++)
#pragma unroll
            for (int q = 0; q < 4; q++) acc[t][j][q] = 0.f;

    const int mrow = w * 16 + (lane & 7) + ((lane >> 3) & 1) * 8;
    const int akb = (lane >> 4) * 16;
    const int krow = (lane >> 4) * 16 + ((lane >> 3) & 1) * 8 + (lane & 7);

    auto wload = [&](int k0, uint32_t bufbase) {
#pragma unroll
        for (int i = tid; i < 768; i += 128) {
            int t = i >> 8, r = (i >> 3) & 31, c = i & 7;
            size_t gi = (size_t)t * EMB * 64 + (size_t)(k0 + r) * 64 + c * 8;
            uint32_t d = bufbase + t * PJ_WTILE + r * PJ_WPITCH + c * 16;
            cp16(sb + d, g_Wh + gi);
            cp16(sb + d + PJ_WSET, g_Wl + gi);
        }
    };

    float4 xv[4], xn[4];
#pragma unroll
    for (int j = 0; j < 4; j++) {
        int i = tid + j * 128, r = i >> 3, c = (i & 7) * 4;
        xv[j] = *reinterpret_cast<const float4*>(&x[(size_t)(m0 + r) * EMB + c]);
    }
    wload(0, PJ_WBASE);
    CP_COMMIT();

    for (int it = 0; it < 32; it++) {
        const int k0 = it * 32;
        const uint32_t wb = PJ_WBASE + (uint32_t)(it & 1) * PJ_WBUF;
        if (it < 31) wload(k0 + 32, PJ_WBASE + (uint32_t)((it + 1) & 1) * PJ_WBUF);
        CP_COMMIT();
        if (it < 31) {
#pragma unroll
            for (int j = 0; j < 4; j++) {
                int i = tid + j * 128, r = i >> 3, c = (i & 7) * 4;
                xn[j] = *reinterpret_cast<const float4*>(&x[(size_t)(m0 + r) * EMB + k0 + 32 + c]);
            }
        }
#pragma unroll
        for (int j = 0; j < 4; j++) {
            int i = tid + j * 128, r = i >> 3, c = (i & 7) * 4;
            uint32_t h0, l0, h1, l1;
            split2(xv[j].x, xv[j].y, h0, l0);
            split2(xv[j].z, xv[j].w, h1, l1);
            uint32_t* ph = reinterpret_cast<uint32_t*>(sm + PJ_XH + r * PJ_XPITCH + c * 2);
            ph[0] = h0; ph[1] = h1;
            uint32_t* pl = reinterpret_cast<uint32_t*>(sm + PJ_XL + r * PJ_XPITCH + c * 2);
            pl[0] = l0; pl[1] = l1;
        }
        CP_WAIT1();
        __syncthreads();

        uint32_t ah[2][4], al[2][4];
#pragma unroll
        for (int kk = 0; kk < 2; kk++) {
            ldsm4(ah[kk], sb + PJ_XH + mrow * PJ_XPITCH + kk * 32 + akb);
            ldsm4(al[kk], sb + PJ_XL + mrow * PJ_XPITCH + kk * 32 + akb);
        }
#pragma unroll
        for (int t = 0; t < 3; t++) {
#pragma unroll
            for (int j = 0; j < 8; j++) {
                uint32_t bh[4], bl[4];
                ldsm4t(bh, sb + wb + t * PJ_WTILE + krow * PJ_WPITCH + j * 16);
                ldsm4t(bl, sb + wb + PJ_WSET + t * PJ_WTILE + krow * PJ_WPITCH + j * 16);
                float* c = acc[t][j];
                mma_bf16(c, ah[0], bh[0], bh[1]);
                mma_bf16(c, ah[1], bh[2], bh[3]);
                mma_bf16(c, ah[0], bl[0], bl[1]);
                mma_bf16(c, ah[1], bl[2], bl[3]);
                mma_bf16(c, al[0], bh[0], bh[1]);
                mma_bf16(c, al[1], bh[2], bh[3]);
            }
        }
        __syncthreads();
#pragma unroll
        for (int j = 0; j < 4; j++) xv[j] = xn[j];
    }

#pragma unroll
    for (int t = 0; t < 3; t++) {
        __nv_bfloat16* dh = (t == 0) ? g_Qh : (t == 1) ? g_Kh : g_Uh;
        __nv_bfloat16* dl = (t == 0) ? g_Ql : (t == 1) ? g_Kl : g_Ul;
        const float scl = (t == 0) ? 0.18033688f : 1.0f;  // 0.125 * log2(e)
#pragma unroll
        for (int j = 0; j < 8; j++) {
            int col = j * 8 + tig * 2;
            size_t r0 = (size_t)(m0 + w * 16 + gr);
            uint32_t h, l;
            split2(acc[t][j][0] * scl, acc[t][j][1] * scl, h, l);
            *reinterpret_cast<uint32_t*>(dh + r0 * 64 + col) = h;
            *reinterpret_cast<uint32_t*>(dl + r0 * 64 + col) = l;
            split2(acc[t][j][2] * scl, acc[t][j][3] * scl, h, l);
            *reinterpret_cast<uint32_t*>(dh + (r0 + 8) * 64 + col) = h;
            *reinterpret_cast<uint32_t*>(dl + (r0 + 8) * 64 + col) = l;
        }
    }
}

// ---------------------------------------------------------------------------
// Kernel 2: FA2 flash attention, split-KV 4 ways, cp.async double-buffered.
// grid (SEQ/64, BATCH, 4); 128 threads. kt = par, par+4, ... <= qt.
// ---------------------------------------------------------------------------
#define FL_PITCH 144
#define FL_TILE (64 * FL_PITCH)       // 9216
#define FL_STAGE (4 * FL_TILE)        // 36864
#define FL_SMEM (2 * FL_STAGE)        // 73728

__global__ __launch_bounds__(128) void flash_kernel()
{
    extern __shared__ char sm[];
    const uint32_t sb = smem_u32(sm);
    const int tid = threadIdx.x, w = tid >> 5, lane = tid & 31;
    const int gr = lane >> 2, tig = lane & 3;
    const int qt = blockIdx.x, b = blockIdx.y, par = blockIdx.z;
    const int q0 = qt * 64;
    const size_t base = (size_t)b * SEQ;

    float* Op = g_Op[par];
    float* lp = g_l[par];
    const size_t r0s = base + q0 + w * 16 + gr;

    if (par > qt) {
        // no KV tiles for this split: write zero partials
        if (tig == 0) { lp[r0s] = 0.f; lp[r0s + 8] = 0.f; }
        float2 z = make_float2(0.f, 0.f);
#pragma unroll
        for (int j = 0; j < 8; j++) {
            int col = j * 8 + tig * 2;
            *reinterpret_cast<float2*>(&Op[r0s * 64 + col]) = z;
            *reinterpret_cast<float2*>(&Op[(r0s + 8) * 64 + col]) = z;
        }
        return;
    }

    // stage Q (64x64 hi/lo) into stage0, pull fragments
    for (int i = tid; i < 64 * 8; i += 128) {
        int r = i >> 3, c = i & 7;
        size_t gq = (base + q0 + r) * 64 + c * 8;
        *reinterpret_cast<uint4*>(sm + r * FL_PITCH + c * 16) =
            *reinterpret_cast<const uint4*>(g_Qh + gq);
        *reinterpret_cast<uint4*>(sm + FL_TILE + r * FL_PITCH + c * 16) =
            *reinterpret_cast<const uint4*>(g_Ql + gq);
    }
    __syncthreads();
    uint32_t qh[4][4], ql[4][4];
    {
        const int mrow = w * 16 + (lane & 7) + ((lane >> 3) & 1) * 8;
        const int akb = (lane >> 4) * 16;
#pragma unroll
        for (int kk = 0; kk < 4; kk++) {
            ldsm4(qh[kk], sb + mrow * FL_PITCH + kk * 32 + akb);
            ldsm4(ql[kk], sb + FL_TILE + mrow * FL_PITCH + kk * 32 + akb);
        }
    }
    __syncthreads();

    auto load_tile = [&](int kt, uint32_t bb) {
        const int k0 = kt * 64;
#pragma unroll
        for (int i = tid; i < 64 * 8; i += 128) {
            int r = i >> 3, c = i & 7;
            uint32_t d = bb + r * FL_PITCH + c * 16;
            size_t gk = (base + k0 + r) * 64 + c * 8;
            cp16(sb + d, g_Kh + gk);
            cp16(sb + d + FL_TILE, g_Kl + gk);
            cp16(sb + d + 2 * FL_TILE, g_Uh + gk);
            cp16(sb + d + 3 * FL_TILE, g_Ul + gk);
        }
    };

    float o[8][4];
#pragma unroll
    for (int j = 0; j < 8; j++)
#pragma unroll
        for (int q = 0; q < 4; q++) o[j][q] = 0.f;
    float l0 = 0.f, l1 = 0.f;

    const int row0 = q0 + w * 16 + gr, row1 = row0 + 8;

    load_tile(par, 0);
    CP_COMMIT();

    int it = 0;
    for (int kt = par; kt <= qt; kt += NSPLIT, it++) {
        const int k0 = kt * 64;
        const uint32_t bb = (uint32_t)(it & 1) * FL_STAGE;
        if (kt + NSPLIT <= qt) load_tile(kt + NSPLIT, (uint32_t)((it + 1) & 1) * FL_STAGE);
        CP_COMMIT();
        CP_WAIT1();
        __syncthreads();

        // S = Q K^T  (split-bf16, 3 passes)
        float s[8][4];
#pragma unroll
        for (int j = 0; j < 8; j++) {
#pragma unroll
            for (int q = 0; q < 4; q++) s[j][q] = 0.f;
            uint32_t a0 = sb + bb + (j * 8 + (lane & 7)) * FL_PITCH + (lane >> 3) * 16;
            uint32_t a1 = a0 + FL_TILE;
            uint32_t bh[4], bh2[4], bl[4], bl2[4];
            ldsm4(bh, a0); ldsm4(bh2, a0 + 64);
            ldsm4(bl, a1); ldsm4(bl2, a1 + 64);
            float* c = s[j];
            mma_bf16(c, qh[0], bh[0], bh[1]);
            mma_bf16(c, qh[1], bh[2], bh[3]);
            mma_bf16(c, qh[2], bh2[0], bh2[1]);
            mma_bf16(c, qh[3], bh2[2], bh2[3]);
            mma_bf16(c, qh[0], bl[0], bl[1]);
            mma_bf16(c, qh[1], bl[2], bl[3]);
            mma_bf16(c, qh[2], bl2[0], bl2[1]);
            mma_bf16(c, qh[3], bl2[2], bl2[3]);
            mma_bf16(c, ql[0], bh[0], bh[1]);
            mma_bf16(c, ql[1], bh[2], bh[3]);
            mma_bf16(c, ql[2], bh2[0], bh2[1]);
            mma_bf16(c, ql[3], bh2[2], bh2[3]);
        }

        // softmax: p = exp2(s); causal mask only on diagonal tile
        const bool diag = (kt == qt);
#pragma unroll
        for (int j = 0; j < 8; j++) {
            int cb = k0 + j * 8 + tig * 2;
            float p0 = ex2(s[j][0]), p1 = ex2(s[j][1]);
            float p2 = ex2(s[j][2]), p3 = ex2(s[j][3]);
            if (diag) {
                if (cb > row0) p0 = 0.f;
                if (cb + 1 > row0) p1 = 0.f;
                if (cb > row1) p2 = 0.f;
                if (cb + 1 > row1) p3 = 0.f;
            }
            s[j][0] = p0; s[j][1] = p1; s[j][2] = p2; s[j][3] = p3;
            l0 += p0 + p1;
            l1 += p2 + p3;
        }

        // P fragments (C-frag -> A-frag identity), hi/lo
        uint32_t ph[4][4], pl[4][4];
#pragma unroll
        for (int kk = 0; kk < 4; kk++) {
            split2(s[2 * kk][0], s[2 * kk][1], ph[kk][0], pl[kk][0]);
            split2(s[2 * kk][2], s[2 * kk][3], ph[kk][1], pl[kk][1]);
            split2(s[2 * kk + 1][0], s[2 * kk + 1][1], ph[kk][2], pl[kk][2]);
            split2(s[2 * kk + 1][2], s[2 * kk + 1][3], ph[kk][3], pl[kk][3]);
        }

        // O += P U (split-bf16, 3 passes)
#pragma unroll
        for (int jp = 0; jp < 4; jp++) {
#pragma unroll
            for (int kk = 0; kk < 4; kk++) {
                int krow = kk * 16 + ((lane >> 3) & 1) * 8 + (lane & 7);
                int nbyte = (jp * 2 + (lane >> 4)) * 16;
                uint32_t bh[4], bl[4];
                ldsm4t(bh, sb + bb + 2 * FL_TILE + krow * FL_PITCH + nbyte);
                ldsm4t(bl, sb + bb + 3 * FL_TILE + krow * FL_PITCH + nbyte);
                mma_bf16(o[2 * jp], ph[kk], bh[0], bh[1]);
                mma_bf16(o[2 * jp + 1], ph[kk], bh[2], bh[3]);
                mma_bf16(o[2 * jp], ph[kk], bl[0], bl[1]);
                mma_bf16(o[2 * jp + 1], ph[kk], bl[2], bl[3]);
                mma_bf16(o[2 * jp], pl[kk], bh[0], bh[1]);
                mma_bf16(o[2 * jp + 1], pl[kk], bh[2], bh[3]);
            }
        }
        __syncthreads();
    }

    l0 += __shfl_xor_sync(0xffffffffu, l0, 1);
    l0 += __shfl_xor_sync(0xffffffffu, l0, 2);
    l1 += __shfl_xor_sync(0xffffffffu, l1, 1);
    l1 += __shfl_xor_sync(0xffffffffu, l1, 2);

    if (tig == 0) { lp[r0s] = l0; lp[r0s + 8] = l1; }
#pragma unroll
    for (int j = 0; j < 8; j++) {
        int col = j * 8 + tig * 2;
        *reinterpret_cast<float2*>(&Op[r0s * 64 + col]) = make_float2(o[j][0], o[j][1]);
        *reinterpret_cast<float2*>(&Op[(r0s + 8) * 64 + col]) = make_float2(o[j][2], o[j][3]);
    }
}

// ---------------------------------------------------------------------------
// Kernel 2b: combine split-KV partials, normalize, emit bf16 hi/lo.
// ---------------------------------------------------------------------------
__global__ __launch_bounds__(256) void combine_kernel()
{
    int i = (blockIdx.x * 256 + threadIdx.x) * 2;
    int row = i >> 6;
    float lsum = g_l[0][row] + g_l[1][row] + g_l[2][row] + g_l[3][row];
    float inv = 1.0f / lsum;
    float v0 = (g_Op[0][i] + g_Op[1][i] + g_Op[2][i] + g_Op[3][i]) * inv;
    float v1 = (g_Op[0][i + 1] + g_Op[1][i + 1] + g_Op[2][i + 1] + g_Op[3][i + 1]) * inv;
    uint32_t h, l;
    split2(v0, v1, h, l);
    *reinterpret_cast<uint32_t*>(g_Oh + i) = h;
    *reinterpret_cast<uint32_t*>(g_Ol + i) = l;
}

// ---------------------------------------------------------------------------
// Kernel 3: out[256 rows x 256 cols] = O64 @ w_v2. A staged once (bf16 hi/lo),
// W processed in two 128-col halves through one buffer. grid (4, 64).
// ---------------------------------------------------------------------------
#define OP_OPITCH 144
#define OP_WPITCH 272
#define OP_AH 0
#define OP_AL (256 * OP_OPITCH)            // 36864
#define OP_WH (2 * 256 * OP_OPITCH)        // 73728
#define OP_WL (OP_WH + 64 * OP_WPITCH)     // 91136
#define OP_SMEM (OP_WL + 64 * OP_WPITCH)   // 108544

__global__ __launch_bounds__(256) void outproj_kernel(float* __restrict__ out)
{
    extern __shared__ char sm[];
    const uint32_t sb = smem_u32(sm);
    const int tid = threadIdx.x, w = tid >> 5, lane = tid & 31;
    const int gr = lane >> 2, tig = lane & 3;
    const int row0 = blockIdx.y * 256, cbase = blockIdx.x * 256;

    // stage A (256x64 bf16 hi/lo)
    for (int i = tid; i < 256 * 8; i += 256) {
        int r = i >> 3, c = i & 7;
        size_t gi = (size_t)(row0 + r) * 64 + c * 8;
        *reinterpret_cast<uint4*>(sm + OP_AH + r * OP_OPITCH + c * 16) =
            *reinterpret_cast<const uint4*>(g_Oh + gi);
        *reinterpret_cast<uint4*>(sm + OP_AL + r * OP_OPITCH + c * 16) =
            *reinterpret_cast<const uint4*>(g_Ol + gi);
    }
    // stage W half 0
    for (int i = tid; i < 64 * 16; i += 256) {
        int r = i >> 4, c = i & 15;
        size_t gi = (size_t)r * EMB + cbase + c * 8;
        *reinterpret_cast<uint4*>(sm + OP_WH + r * OP_WPITCH + c * 16) =
            *reinterpret_cast<const uint4*>(g_W2h + gi);
        *reinterpret_cast<uint4*>(sm + OP_WL + r * OP_WPITCH + c * 16) =
            *reinterpret_cast<const uint4*>(g_W2l + gi);
    }
    __syncthreads();

    // A fragments: warp M=32 (2 m-frags), held across both halves
    uint32_t ah[2][4][4], al[2][4][4];
    const int akb = (lane >> 4) * 16;
#pragma unroll
    for (int m = 0; m < 2; m++) {
        const int mrow = w * 32 + m * 16 + (lane & 7) + ((lane >> 3) & 1) * 8;
#pragma unroll
        for (int kk = 0; kk < 4; kk++) {
            ldsm4(ah[m][kk], sb + OP_AH + mrow * OP_OPITCH + kk * 32 + akb);
            ldsm4(al[m][kk], sb + OP_AL + mrow * OP_OPITCH + kk * 32 + akb);
        }
    }

#pragma unroll
    for (int h = 0; h < 2; h++) {
        if (h == 1) {
            __syncthreads();   // all warps done reading W half 0
            for (int i = tid; i < 64 * 16; i += 256) {
                int r = i >> 4, c = i & 15;
                size_t gi = (size_t)r * EMB + cbase + 128 + c * 8;
                *reinterpret_cast<uint4*>(sm + OP_WH + r * OP_WPITCH + c * 16) =
                    *reinterpret_cast<const uint4*>(g_W2h + gi);
                *reinterpret_cast<uint4*>(sm + OP_WL + r * OP_WPITCH + c * 16) =
                    *reinterpret_cast<const uint4*>(g_W2l + gi);
            }
            __syncthreads();
        }
        const int col0 = cbase + h * 128;
#pragma unroll
        for (int j = 0; j < 16; j++) {
            float c[2][4];
#pragma unroll
            for (int m = 0; m < 2; m++)
#pragma unroll
                for (int q = 0; q < 4; q++) c[m][q] = 0.f;
#pragma unroll
            for (int kp = 0; kp < 2; kp++) {
                int krow = kp * 32 + (lane >> 4) * 16 + ((lane >> 3) & 1) * 8 + (lane & 7);
                uint32_t bh[4], bl[4];
                ldsm4t(bh, sb + OP_WH + krow * OP_WPITCH + j * 16);
                ldsm4t(bl, sb + OP_WL + krow * OP_WPITCH + j * 16);
#pragma unroll
                for (int m = 0; m < 2; m++) {
                    mma_bf16(c[m], ah[m][2 * kp], bh[0], bh[1]);
                    mma_bf16(c[m], ah[m][2 * kp + 1], bh[2], bh[3]);
                    mma_bf16(c[m], ah[m][2 * kp], bl[0], bl[1]);
                    mma_bf16(c[m], ah[m][2 * kp + 1], bl[2], bl[3]);
                    mma_bf16(c[m], al[m][2 * kp], bh[0], bh[1]);
                    mma_bf16(c[m], al[m][2 * kp + 1], bh[2], bh[3]);
                }
            }
            int col = col0 + j * 8 + tig * 2;
#pragma unroll
            for (int m = 0; m < 2; m++) {
                int r = row0 + w * 32 + m * 16 + gr;
                *reinterpret_cast<float2*>(&out[(size_t)r * EMB + col]) =
                    make_float2(c[m][0], c[m][1]);
                *reinterpret_cast<float2*>(&out[(size_t)(r + 8) * EMB + col]) =
                    make_float2(c[m][2], c[m][3]);
            }
        }
    }
}

// ---------------------------------------------------------------------------
extern "C" void kernel_launch(void* const* d_in, const int* in_sizes, int n_in,
                              void* d_out, int out_size)
{
    const float* x    = (const float*)d_in[0];
    const float* w_q  = (const float*)d_in[1];
    const float* w_k  = (const float*)d_in[2];
    const float* w_v1 = (const float*)d_in[3];
    const float* w_v2 = (const float*)d_in[4];
    float* out = (float*)d_out;
    (void)in_sizes; (void)n_in; (void)out_size;

    cudaFuncSetAttribute(proj_kernel, cudaFuncAttributeMaxDynamicSharedMemorySize, PJ_SMEM);
    cudaFuncSetAttribute(flash_kernel, cudaFuncAttributeMaxDynamicSharedMemorySize, FL_SMEM);
    cudaFuncSetAttribute(outproj_kernel, cudaFuncAttributeMaxDynamicSharedMemorySize, OP_SMEM);

    convw_kernel<<<512, 256>>>(w_q, w_k, w_v1, w_v2);
    proj_kernel<<<MTOT / 64, 128, PJ_SMEM>>>(x);
    flash_kernel<<<dim3(SEQ / 64, BATCH, NSPLIT), 128, FL_SMEM>>>();
    combine_kernel<<<MTOT * DHEAD / 512, 256>>>();
    outproj_kernel<<<dim3(EMB / 256, MTOT / 256), 256, OP_SMEM>>>(out);
}